// round 15
// baseline (speedup 1.0000x reference)
#include <cuda_runtime.h>
#include <cuda_fp16.h>
#include <mma.h>
#include <math.h>
#include <stdint.h>

using namespace nvcuda;

#define NN 50000
#define NE 600000
#define FIN 128
#define HID 64
#define C1 256
#define SENTD 768

#define AS_LDM 24    /* halves; 48B row stride -> conflict-free ldmatrix */
#define BS2_LDM 72   /* halves; 144B stride -> conflict-free */

// ---------------- streams/events (created at load; no device memory) ----------------
static cudaStream_t g_s1 = 0;
static cudaEvent_t g_e0 = 0, g_e1 = 0;
namespace {
struct SideStreamInit {
    SideStreamInit() {
        if (cudaStreamCreateWithFlags(&g_s1, cudaStreamNonBlocking) != cudaSuccess) g_s1 = 0;
        cudaEventCreateWithFlags(&g_e0, cudaEventDisableTiming);
        cudaEventCreateWithFlags(&g_e1, cudaEventDisableTiming);
    }
};
SideStreamInit g_side_stream_init;
}

// ---------------- device scratch ----------------
__device__ __align__(16) __half g_xh   [(size_t)(NN + 64) * FIN]; // fp16 x (padded)
__device__ __align__(16) __half g_h1f16[(size_t)NN * C1];         // fp16 x@W1
__device__ __align__(16) __half g_out1h[(size_t)(NN + 64) * C1];  // fp16 LN(elu(agg1+b1)) (padded)
__device__ __align__(16) __half g_h2f16[(size_t)NN * HID];        // fp16 h1n@W2
__device__ __align__(16) float g_es1[NN * 4];
__device__ __align__(16) float g_ed1[NN * 4];
__device__ float g_es2[NN], g_ed2[NN];
__device__ float g_sent[HID];
__device__ int g_done;   // agg2 completion counter (self-resets)
// CSR (g_deg zero-initialized at load; re-zeroed by agg1 each call)
__device__ int g_deg[NN];
__device__ int g_rowstart[NN + 1];
__device__ int g_fill[NN];
__device__ int g_csrc[NE];
__device__ int g_eorig[NE];

// ---------------- helpers ----------------
__device__ __forceinline__ float warp_sum(float v) {
    #pragma unroll
    for (int o = 16; o; o >>= 1) v += __shfl_xor_sync(0xffffffffu, v, o);
    return v;
}
__device__ __forceinline__ float lrelu02(float v) { return v > 0.f ? v : 0.2f * v; }
__device__ __forceinline__ float fexp(float v) { return __expf(v); }

__device__ __forceinline__ void cp_async16(void* smem, const void* gmem) {
    unsigned s = (unsigned)__cvta_generic_to_shared(smem);
    asm volatile("cp.async.cg.shared.global [%0], [%1], 16;\n" :: "r"(s), "l"(gmem));
}
__device__ __forceinline__ void cp_commit() { asm volatile("cp.async.commit_group;\n"); }
__device__ __forceinline__ void cp_wait0()  { asm volatile("cp.async.wait_group 0;\n"); }

__device__ __forceinline__ uint4 packh8(float4 a, float4 b) {
    __half2 h0 = __floats2half2_rn(a.x, a.y);
    __half2 h1 = __floats2half2_rn(a.z, a.w);
    __half2 h2 = __floats2half2_rn(b.x, b.y);
    __half2 h3 = __floats2half2_rn(b.z, b.w);
    return make_uint4(*(unsigned*)&h0, *(unsigned*)&h1, *(unsigned*)&h2, *(unsigned*)&h3);
}

// ================= x -> fp16 conversion =================
__global__ __launch_bounds__(256) void x2h(const float* __restrict__ x) {
    int i = blockIdx.x * blockDim.x + threadIdx.x;
    if (i >= NN * FIN / 8) return;
    const float4* src = (const float4*)x + i * 2;
    float4 a = src[0], b = src[1];
    ((uint4*)g_xh)[i] = packh8(a, b);
}

// ================= CSR build =================
__global__ void k_hist(const int* __restrict__ ei) {
    int e4 = blockIdx.x * blockDim.x + threadIdx.x;
    if (e4 >= NE / 4) return;
    int4 d = ((const int4*)(ei + NE))[e4];
    atomicAdd(&g_deg[d.x], 1);
    atomicAdd(&g_deg[d.y], 1);
    atomicAdd(&g_deg[d.z], 1);
    atomicAdd(&g_deg[d.w], 1);
}

__global__ void k_scan() {
    __shared__ int wsum[32];
    __shared__ int stot;
    const int t = threadIdx.x, lane = t & 31, w = t >> 5;
    int base = 0;
    for (int c = 0; c < 13; c++) {
        int i4 = c * 1024 + t;
        int4 v = (i4 < NN / 4) ? ((const int4*)g_deg)[i4] : make_int4(0, 0, 0, 0);
        int tot = v.x + v.y + v.z + v.w;
        int inc = tot;
        #pragma unroll
        for (int o = 1; o < 32; o <<= 1) {
            int x = __shfl_up_sync(0xffffffffu, inc, o);
            if (lane >= o) inc += x;
        }
        if (lane == 31) wsum[w] = inc;
        __syncthreads();
        if (w == 0) {
            int x = wsum[lane];
            int incw = x;
            #pragma unroll
            for (int o = 1; o < 32; o <<= 1) {
                int y = __shfl_up_sync(0xffffffffu, incw, o);
                if (lane >= o) incw += y;
            }
            wsum[lane] = incw;
            if (lane == 31) stot = incw;
        }
        __syncthreads();
        int excl = base + (w ? wsum[w - 1] : 0) + inc - tot;
        if (i4 < NN / 4) {
            int idx = i4 * 4;
            int e0 = excl, e1 = e0 + v.x, e2 = e1 + v.y, e3 = e2 + v.z;
            g_rowstart[idx] = e0; g_rowstart[idx + 1] = e1;
            g_rowstart[idx + 2] = e2; g_rowstart[idx + 3] = e3;
            g_fill[idx] = e0; g_fill[idx + 1] = e1;
            g_fill[idx + 2] = e2; g_fill[idx + 3] = e3;
        }
        base += stot;
        __syncthreads();
    }
    if (t == 0) g_rowstart[NN] = NE;
}

__global__ void k_fill(const int* __restrict__ ei) {
    int e4 = blockIdx.x * blockDim.x + threadIdx.x;
    if (e4 >= NE / 4) return;
    int4 s4 = ((const int4*)ei)[e4];
    int4 d4 = ((const int4*)(ei + NE))[e4];
    int e = e4 * 4;
    int p;
    p = atomicAdd(&g_fill[d4.x], 1); g_csrc[p] = s4.x; g_eorig[p] = e;
    p = atomicAdd(&g_fill[d4.y], 1); g_csrc[p] = s4.y; g_eorig[p] = e + 1;
    p = atomicAdd(&g_fill[d4.z], 1); g_csrc[p] = s4.z; g_eorig[p] = e + 2;
    p = atomicAdd(&g_fill[d4.w], 1); g_csrc[p] = s4.w; g_eorig[p] = e + 3;
}

// ================= GEMM1 tensor-core fused (persistent B, A via cp.async) ==============
// BM=128 BN=64 BK=16, 8 warps, 2 blocks/SM
#define G1_A_BYTES (128 * AS_LDM * 2)             /* 6144  */
#define G1_B_OFF   (2 * G1_A_BYTES)               /* 12288 */
#define G1_TOTAL   (G1_B_OFF + 128 * BS2_LDM * 2) /* 30720 */

__global__ __launch_bounds__(256, 2) void gemm1_tc(const float* __restrict__ B,
        const float* __restrict__ asrc, const float* __restrict__ adst) {
    __shared__ __align__(16) char sm[G1_TOTAL];
    const int tid = threadIdx.x;
    const int w = tid >> 5, lane = tid & 31;
    const int bm = blockIdx.y * 128, bn = blockIdx.x * 64;

    wmma::fragment<wmma::accumulator, 16, 16, 16, float> acc[4];
    #pragma unroll
    for (int n = 0; n < 4; n++) wmma::fill_fragment(acc[n], 0.f);

    const int ar = tid >> 1, ac = (tid & 1) * 8;

    // A stage-0 prologue
    cp_async16((__half*)(sm) + ar * AS_LDM + ac, &g_xh[(size_t)(bm + ar) * FIN + ac]);
    cp_commit();

    // persistent B: whole 128x64 fp32 block -> fp16 smem (row = K)
    __half* Bsp = (__half*)(sm + G1_B_OFF);
    {
        const int r = tid >> 1, cb = (tid & 1) * 32;
        const float* bp = B + (size_t)r * C1 + bn + cb;
        #pragma unroll
        for (int u = 0; u < 4; u++) {
            float4 f0 = *(const float4*)(bp + u * 8);
            float4 f1 = *(const float4*)(bp + u * 8 + 4);
            *(uint4*)&Bsp[r * BS2_LDM + cb + u * 8] = packh8(f0, f1);
        }
    }

    for (int ks = 0; ks < 8; ks++) {
        const int st = ks & 1;
        __half* Asp = (__half*)(sm + st * G1_A_BYTES);
        cp_wait0();
        __syncthreads();                       // A[st] ready; B ready (iter 0)
        if (ks < 7) {
            int k0 = (ks + 1) * 16;
            cp_async16((__half*)(sm + (st ^ 1) * G1_A_BYTES) + ar * AS_LDM + ac,
                       &g_xh[(size_t)(bm + ar) * FIN + k0 + ac]);
            cp_commit();
        }
        wmma::fragment<wmma::matrix_a, 16, 16, 16, __half, wmma::row_major> af;
        wmma::load_matrix_sync(af, &Asp[(w * 16) * AS_LDM], AS_LDM);
        #pragma unroll
        for (int n = 0; n < 4; n++) {
            wmma::fragment<wmma::matrix_b, 16, 16, 16, __half, wmma::row_major> bf;
            wmma::load_matrix_sync(bf, &Bsp[(ks * 16) * BS2_LDM + n * 16], BS2_LDM);
            wmma::mma_sync(acc[n], af, bf, acc[n]);
        }
        __syncthreads();                       // protect A[st] reads vs next overwrite
    }

    float* bufw = (float*)(sm + w * (16 * 36 * 4));
    const int row = lane >> 1, cb = (lane & 1) * 16;
    const int gr = bm + w * 16 + row;
    const int headg = blockIdx.x;
    float es = 0.f, ed = 0.f;
    #pragma unroll
    for (int qq = 0; qq < 2; qq++) {
        wmma::store_matrix_sync(bufw,      acc[2 * qq],     36, wmma::mem_row_major);
        wmma::store_matrix_sync(bufw + 16, acc[2 * qq + 1], 36, wmma::mem_row_major);
        __syncwarp();
        const int colg = qq * 32 + cb;
        unsigned pk[8];
        #pragma unroll
        for (int c = 0; c < 8; c++) {
            float2 v = *(float2*)&bufw[row * 36 + cb + c * 2];
            float2 sa = *(const float2*)&asrc[headg * 64 + colg + c * 2];
            float2 da = *(const float2*)&adst[headg * 64 + colg + c * 2];
            es += v.x * sa.x + v.y * sa.y;
            ed += v.x * da.x + v.y * da.y;
            __half2 hh = __floats2half2_rn(v.x, v.y);
            pk[c] = *(unsigned*)&hh;
        }
        if (gr < NN) {
            uint4* dst = (uint4*)&g_h1f16[(size_t)gr * C1 + bn + colg];
            dst[0] = make_uint4(pk[0], pk[1], pk[2], pk[3]);
            dst[1] = make_uint4(pk[4], pk[5], pk[6], pk[7]);
        }
        __syncwarp();
    }
    float es2 = es + __shfl_xor_sync(0xffffffffu, es, 1);
    float ed2 = ed + __shfl_xor_sync(0xffffffffu, ed, 1);
    if (gr < NN && (lane & 1) == 0) {
        g_es1[gr * 4 + headg] = es2;
        g_ed1[gr * 4 + headg] = ed2;
    }
}

// ================= GEMM2 tensor-core fused =================
#define AS2_BYTES (128 * AS_LDM * 2)
#define BS2_BYTES (16 * BS2_LDM * 2)
#define SM2_AS(st) (st ? AS2_BYTES : 0)
#define SM2_BS(st) (2 * AS2_BYTES + (st ? BS2_BYTES : 0))
#define SM2_TOTAL  (8 * 16 * 36 * 4)

__global__ __launch_bounds__(256) void gemm2_tc(const float* __restrict__ B,
        const float* __restrict__ asrc, const float* __restrict__ adst) {
    __shared__ __align__(16) char sm[SM2_TOTAL];
    const int tid = threadIdx.x;
    const int w = tid >> 5, lane = tid & 31;
    const int bm = blockIdx.x * 128;

    wmma::fragment<wmma::accumulator, 16, 16, 16, float> acc[4];
    #pragma unroll
    for (int n = 0; n < 4; n++) wmma::fill_fragment(acc[n], 0.f);

    const int ar = tid >> 1, ac = (tid & 1) * 8;
    const int bkr = tid >> 4, bnc = (tid & 15) * 4;

    cp_async16((__half*)(sm + SM2_AS(0)) + ar * AS_LDM + ac,
               &g_out1h[(size_t)(bm + ar) * C1 + ac]);
    cp_commit();
    float4 bb = *(const float4*)&B[(size_t)bkr * HID + bnc];

    for (int ks = 0; ks < 16; ks++) {
        const int st = ks & 1;
        __half* Asp = (__half*)(sm + SM2_AS(st));
        __half* Bsp = (__half*)(sm + SM2_BS(st));
        {
            __half2 p0 = __floats2half2_rn(bb.x, bb.y);
            __half2 p1 = __floats2half2_rn(bb.z, bb.w);
            *(uint2*)&Bsp[bkr * BS2_LDM + bnc] = make_uint2(*(unsigned*)&p0, *(unsigned*)&p1);
        }
        cp_wait0();
        __syncthreads();
        if (ks < 15) {
            int k0 = (ks + 1) * 16;
            cp_async16((__half*)(sm + SM2_AS(st ^ 1)) + ar * AS_LDM + ac,
                       &g_out1h[(size_t)(bm + ar) * C1 + k0 + ac]);
            cp_commit();
            bb = *(const float4*)&B[(size_t)(k0 + bkr) * HID + bnc];
        }
        wmma::fragment<wmma::matrix_a, 16, 16, 16, __half, wmma::row_major> af;
        wmma::load_matrix_sync(af, &Asp[(w * 16) * AS_LDM], AS_LDM);
        #pragma unroll
        for (int n = 0; n < 4; n++) {
            wmma::fragment<wmma::matrix_b, 16, 16, 16, __half, wmma::row_major> bf;
            wmma::load_matrix_sync(bf, &Bsp[n * 16], BS2_LDM);
            wmma::mma_sync(acc[n], af, bf, acc[n]);
        }
        __syncthreads();
    }

    float* bufw = (float*)(sm + w * (16 * 36 * 4));
    const int row = lane >> 1, cb = (lane & 1) * 16;
    const int gr = bm + w * 16 + row;
    float es = 0.f, ed = 0.f;
    #pragma unroll
    for (int qq = 0; qq < 2; qq++) {
        wmma::store_matrix_sync(bufw,      acc[2 * qq],     36, wmma::mem_row_major);
        wmma::store_matrix_sync(bufw + 16, acc[2 * qq + 1], 36, wmma::mem_row_major);
        __syncwarp();
        const int colg = qq * 32 + cb;
        unsigned pk[8];
        #pragma unroll
        for (int c = 0; c < 8; c++) {
            float2 v = *(float2*)&bufw[row * 36 + cb + c * 2];
            float2 sa = *(const float2*)&asrc[colg + c * 2];
            float2 da = *(const float2*)&adst[colg + c * 2];
            es += v.x * sa.x + v.y * sa.y;
            ed += v.x * da.x + v.y * da.y;
            __half2 hh = __floats2half2_rn(v.x, v.y);
            pk[c] = *(unsigned*)&hh;
        }
        if (gr < NN) {
            uint4* dst = (uint4*)&g_h2f16[(size_t)gr * HID + colg];
            dst[0] = make_uint4(pk[0], pk[1], pk[2], pk[3]);
            dst[1] = make_uint4(pk[4], pk[5], pk[6], pk[7]);
        }
        __syncwarp();
    }
    float es2 = es + __shfl_xor_sync(0xffffffffu, es, 1);
    float ed2 = ed + __shfl_xor_sync(0xffffffffu, ed, 1);
    if (gr < NN && (lane & 1) == 0) { g_es2[gr] = es2; g_ed2[gr] = ed2; }
}

// ================= layer-1 aggregation =================
__global__ __launch_bounds__(256) void agg1(const float* __restrict__ b1,
        const float* __restrict__ lng, const float* __restrict__ lnb) {
    const int lane = threadIdx.x & 31;
    const int d = blockIdx.x * 8 + (threadIdx.x >> 5);   // NN = 6250*8 exact
    const int r0 = g_rowstart[d], r1 = g_rowstart[d + 1];
    const int hh = lane & 3, q = lane >> 2;
    const int h = lane >> 3;
    const float edd = g_ed1[d * 4 + hh];
    const float ess = g_es1[d * 4 + hh];
    if (lane == 0) g_deg[d] = 0;
    const __half* __restrict__ hbase = g_h1f16 + lane * 8;

    float acc[8];
    #pragma unroll
    for (int i = 0; i < 8; i++) acc[i] = 0.f;
    float den = 0.f;
    for (int base = r0; base < r1; base += 8) {
        int cnt = min(8, r1 - base);
        int s = 0; float ex = 0.f;
        if (q < cnt) {
            s = g_csrc[base + q];
            ex = fexp(lrelu02(g_es1[s * 4 + hh] + edd));
        }
        den += ex;
        for (int q2 = 0; q2 < cnt; q2++) {
            unsigned ss = (unsigned)__shfl_sync(0xffffffffu, s, q2 * 4);
            float a = __shfl_sync(0xffffffffu, ex, q2 * 4 + h);
            uint4 pk = *(const uint4*)(hbase + (ss << 8));
            float2 f0 = __half22float2(*(__half2*)&pk.x);
            float2 f1 = __half22float2(*(__half2*)&pk.y);
            float2 f2 = __half22float2(*(__half2*)&pk.z);
            float2 f3 = __half22float2(*(__half2*)&pk.w);
            acc[0] += f0.x * a; acc[1] += f0.y * a;
            acc[2] += f1.x * a; acc[3] += f1.y * a;
            acc[4] += f2.x * a; acc[5] += f2.y * a;
            acc[6] += f3.x * a; acc[7] += f3.y * a;
        }
    }
    den += __shfl_xor_sync(0xffffffffu, den, 4);
    den += __shfl_xor_sync(0xffffffffu, den, 8);
    den += __shfl_xor_sync(0xffffffffu, den, 16);
    float exs = fexp(lrelu02(ess + edd));
    float rd = 1.f / (den + exs + 1e-16f);
    float rdh = __shfl_sync(0xffffffffu, rd, h);
    float exh = __shfl_sync(0xffffffffu, exs, h);

    uint4 pks = *(const uint4*)(hbase + ((unsigned)d << 8));
    float2 s0 = __half22float2(*(__half2*)&pks.x);
    float2 s1 = __half22float2(*(__half2*)&pks.y);
    float2 s2 = __half22float2(*(__half2*)&pks.z);
    float2 s3 = __half22float2(*(__half2*)&pks.w);
    float sf[8] = { s0.x, s0.y, s1.x, s1.y, s2.x, s2.y, s3.x, s3.y };

    float4 bb0 = ((const float4*)b1)[lane * 2], bb1 = ((const float4*)b1)[lane * 2 + 1];
    float bb[8] = { bb0.x, bb0.y, bb0.z, bb0.w, bb1.x, bb1.y, bb1.z, bb1.w };
    float v[8], sum1 = 0.f, sum2 = 0.f;
    #pragma unroll
    for (int i = 0; i < 8; i++) {
        v[i] = (acc[i] + exh * sf[i]) * rdh + bb[i];
        v[i] = v[i] > 0.f ? v[i] : (fexp(v[i]) - 1.f);
        sum1 += v[i]; sum2 += v[i] * v[i];
    }
    sum1 = warp_sum(sum1); sum2 = warp_sum(sum2);
    float mu = sum1 * (1.f / C1);
    float rs = rsqrtf(sum2 * (1.f / C1) - mu * mu + 1e-5f);
    float4 g0 = ((const float4*)lng)[lane * 2], g1 = ((const float4*)lng)[lane * 2 + 1];
    float4 q0 = ((const float4*)lnb)[lane * 2], q1 = ((const float4*)lnb)[lane * 2 + 1];
    float gg[8] = { g0.x, g0.y, g0.z, g0.w, g1.x, g1.y, g1.z, g1.w };
    float qq[8] = { q0.x, q0.y, q0.z, q0.w, q1.x, q1.y, q1.z, q1.w };
    float o[8];
    #pragma unroll
    for (int i = 0; i < 8; i++) o[i] = (v[i] - mu) * rs * gg[i] + qq[i];
    *(uint4*)&g_out1h[(size_t)d * C1 + lane * 8] =
        packh8(make_float4(o[0], o[1], o[2], o[3]),
               make_float4(o[4], o[5], o[6], o[7]));
}

// ================= layer-2 aggregation + fused dueling head (last block) ===============
__global__ __launch_bounds__(256) void agg2(const float* __restrict__ b2,
        const float* __restrict__ lng, const float* __restrict__ lnb,
        float* __restrict__ h2out, float* __restrict__ alpha_out,
        const int* __restrict__ activep,
        const float* __restrict__ fc3w, const float* __restrict__ fc3b,
        const float* __restrict__ valw, const float* __restrict__ valb,
        const float* __restrict__ advw, const float* __restrict__ advb,
        const float* __restrict__ lnfg, const float* __restrict__ lnfb,
        float* __restrict__ outlogits) {
    const int lane = threadIdx.x & 31;
    const int d = blockIdx.x * 8 + (threadIdx.x >> 5);
    const int r0 = g_rowstart[d], r1 = g_rowstart[d + 1];
    const float edd = g_ed2[d];
    const __half* __restrict__ hbase = g_h2f16 + lane * 2;

    float2 acc = make_float2(0.f, 0.f);
    float den = 0.f;
    for (int base = r0; base < r1; base += 32) {
        int cnt = min(32, r1 - base);
        int s = 0; float ex = 0.f;
        if (lane < cnt) {
            s = g_csrc[base + lane];
            ex = fexp(lrelu02(g_es2[s] + edd));
        }
        den += ex;
        for (int q2 = 0; q2 < cnt; q2++) {
            unsigned ss = (unsigned)__shfl_sync(0xffffffffu, s, q2);
            float a = __shfl_sync(0xffffffffu, ex, q2);
            unsigned pk = *(const unsigned*)(hbase + (ss << 6));
            float2 v = __half22float2(*(__half2*)&pk);
            acc.x += v.x * a; acc.y += v.y * a;
        }
    }
    den = warp_sum(den);
    float exs = fexp(lrelu02(g_es2[d] + edd));
    float rd = 1.f / (den + exs + 1e-16f);
    if (lane == 0) alpha_out[NE + d] = exs * rd;
    for (int p = r0 + lane; p < r1; p += 32) {
        int sp = g_csrc[p];
        alpha_out[g_eorig[p]] = fexp(lrelu02(g_es2[sp] + edd)) * rd;
    }
    unsigned pks = *(const unsigned*)(hbase + ((unsigned)d << 6));
    float2 hs = __half22float2(*(__half2*)&pks);
    float2 bb = *(const float2*)&b2[lane * 2];
    float v0 = (acc.x + exs * hs.x) * rd + bb.x;
    float v1 = (acc.y + exs * hs.y) * rd + bb.y;
    float s1 = warp_sum(v0 + v1);
    float s2 = warp_sum(v0 * v0 + v1 * v1);
    float mu = s1 * (1.f / HID);
    float rs = rsqrtf(s2 * (1.f / HID) - mu * mu + 1e-5f);
    float2 gg = *(const float2*)&lng[lane * 2];
    float2 qq = *(const float2*)&lnb[lane * 2];
    *(float2*)&h2out[(size_t)d * HID + lane * 2] =
        make_float2((v0 - mu) * rs * gg.x + qq.x, (v1 - mu) * rs * gg.y + qq.y);

    // ---- last-block-done: run dueling head ----
    __shared__ int sdone;
    __threadfence();
    __syncthreads();
    if (threadIdx.x == 0) {
        int old = atomicAdd(&g_done, 1);
        sdone = (old == (int)gridDim.x - 1);
        if (sdone) g_done = 0;      // reset for next invocation (deterministic)
    }
    __syncthreads();
    if (!sdone) return;
    __threadfence();

    __shared__ float sh[128];
    __shared__ float sh2[64];
    __shared__ float red[8][64];
    __shared__ float st[8];
    const int t = threadIdx.x;
    const int act = activep[0];
    {
        float a = 0.f;
        if (t < 128) a = (t < 64) ? h2out[(size_t)act * 64 + t] : g_sent[t - 64];
        float a1 = warp_sum(t < 128 ? a : 0.f), a2 = warp_sum(t < 128 ? a * a : 0.f);
        if (t < 128 && (t & 31) == 0) { st[t >> 5] = a1; st[4 + (t >> 5)] = a2; }
        __syncthreads();
        float mu2 = (st[0] + st[1] + st[2] + st[3]) / 128.f;
        float rs2 = rsqrtf((st[4] + st[5] + st[6] + st[7]) / 128.f - mu2 * mu2 + 1e-5f);
        if (t < 128) sh[t] = (a - mu2) * rs2 * lnfg[t] + lnfb[t];
    }
    __syncthreads();
    {
        const int c = t & 63, part = t >> 6;
        float u = 0.f;
        int kb = part * 32;
        #pragma unroll 8
        for (int k = 0; k < 32; k++) u += sh[kb + k] * fc3w[(kb + k) * 64 + c];
        red[part][c] = u;
    }
    __syncthreads();
    if (t < 64) {
        float u = red[0][t] + red[1][t] + red[2][t] + red[3][t] + fc3b[t];
        u = fmaxf(u, 0.f);
        float a1 = warp_sum(u), a2 = warp_sum(u * u);
        if ((t & 31) == 0) { st[t >> 5] = a1; st[4 + (t >> 5)] = a2; }
        __syncthreads();
        float mu2 = (st[0] + st[1]) / 64.f;
        float rs2 = rsqrtf((st[4] + st[5]) / 64.f - mu2 * mu2 + 1e-5f);
        sh2[t] = (u - mu2) * rs2 * lng[t] + lnb[t];
    } else { __syncthreads(); }
    __syncthreads();
    {
        float pv = (t < 64) ? sh2[t] * valw[t] : 0.f;
        float a1 = warp_sum(pv);
        if (t < 64 && (t & 31) == 0) st[6 + (t >> 5)] = a1;
    }
    {
        const int c = t & 31, part = t >> 5;
        float u = 0.f;
        int kb = part * 8;
        #pragma unroll
        for (int k = 0; k < 8; k++) u += sh2[kb + k] * advw[(kb + k) * 32 + c];
        red[part][c] = u;
    }
    __syncthreads();
    float val = st[6] + st[7] + valb[0];
    float advv = 0.f;
    if (t < 32) {
        advv = advb[t];
        #pragma unroll
        for (int p = 0; p < 8; p++) advv += red[p][t];
    }
    float m = warp_sum(t < 32 ? advv : 0.f) * (1.f / 32.f);
    if (t < 32) outlogits[t] = tanhf(val + advv - m);
}

// ================= sentence/step path =================
__global__ __launch_bounds__(1024) void sent_kernel(const float* __restrict__ semb,
        const int* __restrict__ stepp,
        const float* __restrict__ fc0w, const float* __restrict__ fc0b,
        const float* __restrict__ fc1w, const float* __restrict__ fc1b,
        const float* __restrict__ fc2w, const float* __restrict__ fc2b,
        const float* __restrict__ lng, const float* __restrict__ lnb) {
    __shared__ float red[16][64];
    __shared__ float sh[64];
    __shared__ float st[2];
    const int t = threadIdx.x, c = t & 63, part = t >> 6;
    const float sval = (float)(stepp[0] + 1) * 0.01f;

    {
        float u = 0.f;
        int kb = part * 48;
        #pragma unroll 8
        for (int k = 0; k < 48; k++) u += semb[kb + k] * fc1w[(kb + k) * 64 + c];
        red[part][c] = u;
    }
    float steps_c = 0.f;
    {
        float tv = (t < 64) ? fmaxf(sval * fc0w[t] + fc0b[t], 0.f) : 0.f;
        float a1 = warp_sum(tv), a2 = warp_sum(tv * tv);
        if (t < 64 && (t & 31) == 0) { sh[t >> 5] = a1; sh[2 + (t >> 5)] = a2; }
        __syncthreads();
        float mu = (sh[0] + sh[1]) / 64.f;
        float rs = rsqrtf((sh[2] + sh[3]) / 64.f - mu * mu + 1e-5f);
        if (t < 64) steps_c = (tv - mu) * rs * lng[t] + lnb[t];
    }
    __syncthreads();
    if (t < 64) {
        float u = fc1b[t];
        #pragma unroll
        for (int p = 0; p < 16; p++) u += red[p][t];
        u = fmaxf(u, 0.f);
        float a1 = warp_sum(u), a2 = warp_sum(u * u);
        if ((t & 31) == 0) { st[t >> 5] = a1; red[15][62 + (t >> 5)] = a2; }
        __syncthreads();
        float mu = (st[0] + st[1]) / 64.f;
        float rs = rsqrtf((red[15][62] + red[15][63]) / 64.f - mu * mu + 1e-5f);
        sh[t] = (u - mu) * rs * lng[t] + lnb[t] + steps_c;
    } else { __syncthreads(); }
    __syncthreads();
    if (t < 256) {
        float u = 0.f;
        int kb = (part & 3) * 16;
        #pragma unroll
        for (int k = 0; k < 16; k++) u += sh[kb + k] * fc2w[(kb + k) * 64 + c];
        red[part & 3][c] = u;
    }
    __syncthreads();
    if (t < 64) {
        float u = red[0][t] + red[1][t] + red[2][t] + red[3][t] + fc2b[t];
        u = fmaxf(u, 0.f);
        float a1 = warp_sum(u), a2 = warp_sum(u * u);
        if ((t & 31) == 0) { st[t >> 5] = a1; red[15][62 + (t >> 5)] = a2; }
        __syncthreads();
        float mu = (st[0] + st[1]) / 64.f;
        float rs = rsqrtf((red[15][62] + red[15][63]) / 64.f - mu * mu + 1e-5f);
        g_sent[t] = (u - mu) * rs * lng[t] + lnb[t];
    }
}

// ================= launch (fork/join: CSR+sent on side stream ∥ x2h+GEMM1 on main) =====
extern "C" void kernel_launch(void* const* d_in, const int* in_sizes, int n_in,
                              void* d_out, int out_size) {
    const float* x      = (const float*)d_in[0];
    const int*   ei     = (const int*)d_in[1];
    const float* semb   = (const float*)d_in[2];
    const int*   active = (const int*)d_in[3];
    const int*   step   = (const int*)d_in[4];
    const float* W1     = (const float*)d_in[5];
    const float* asrc1  = (const float*)d_in[6];
    const float* adst1  = (const float*)d_in[7];
    const float* b1     = (const float*)d_in[8];
    const float* W2     = (const float*)d_in[9];
    const float* asrc2  = (const float*)d_in[10];
    const float* adst2  = (const float*)d_in[11];
    const float* b2     = (const float*)d_in[12];
    const float* fc0w   = (const float*)d_in[13];
    const float* fc0b   = (const float*)d_in[14];
    const float* fc1w   = (const float*)d_in[15];
    const float* fc1b   = (const float*)d_in[16];
    const float* fc2w   = (const float*)d_in[17];
    const float* fc2b   = (const float*)d_in[18];
    const float* fc3w   = (const float*)d_in[19];
    const float* fc3b   = (const float*)d_in[20];
    const float* valw   = (const float*)d_in[21];
    const float* valb   = (const float*)d_in[22];
    const float* advw   = (const float*)d_in[23];
    const float* advb   = (const float*)d_in[24];
    const float* lnhg   = (const float*)d_in[25];
    const float* lnhb   = (const float*)d_in[26];
    const float* lnfg   = (const float*)d_in[27];
    const float* lnfb   = (const float*)d_in[28];
    const float* lnag   = (const float*)d_in[29];
    const float* lnab   = (const float*)d_in[30];
    float* out = (float*)d_out;

    float* h2out     = out + 32;
    float* alpha_out = out + 32 + (size_t)NN * HID;

    cudaStream_t s1 = g_s1;   // 0 fallback -> fully serial, still correct

    // fork
    cudaEventRecord(g_e0, 0);
    cudaStreamWaitEvent(s1, g_e0, 0);

    x2h<<<(NN * FIN / 8 + 255) / 256, 256>>>(x);                            // 0 main
    k_hist<<<(NE / 4 + 255) / 256, 256, 0, s1>>>(ei);                       // 1 side
    k_scan<<<1, 1024, 0, s1>>>();                                           // 2 side
    gemm1_tc<<<dim3(4, (NN + 127) / 128), 256>>>(W1, asrc1, adst1);         // 3 main <- profiled
    k_fill<<<(NE / 4 + 255) / 256, 256, 0, s1>>>(ei);                       // 4 side
    sent_kernel<<<1, 1024, 0, s1>>>(semb, step, fc0w, fc0b, fc1w, fc1b,
                                    fc2w, fc2b, lnhg, lnhb);                // 5 side
    cudaEventRecord(g_e1, s1);

    // join, then rest of the pipeline on main stream
    cudaStreamWaitEvent(0, g_e1, 0);
    agg1<<<NN / 8, 256>>>(b1, lnag, lnab);                                  // 6
    gemm2_tc<<<(NN + 127) / 128, 256>>>(W2, asrc2, adst2);                  // 7
    agg2<<<NN / 8, 256>>>(b2, lnhg, lnhb, h2out, alpha_out,
                          active, fc3w, fc3b, valw, valb, advw, advb,
                          lnfg, lnfb, out);                                 // 8 (+head)
}

// round 16
// speedup vs baseline: 1.0869x; 1.0869x over previous
#include <cuda_runtime.h>
#include <cuda_fp16.h>
#include <mma.h>
#include <math.h>
#include <stdint.h>

using namespace nvcuda;

#define NN 50000
#define NE 600000
#define FIN 128
#define HID 64
#define C1 256
#define SENTD 768

#define AS_LDM 24    /* halves; 48B row stride -> conflict-free ldmatrix */
#define BS2_LDM 72   /* halves; 144B stride -> conflict-free */

// ---------------- streams/events (created at load; no device memory) ----------------
static cudaStream_t g_s1 = 0;
static cudaEvent_t g_e0 = 0, g_e1 = 0;
namespace {
struct SideStreamInit {
    SideStreamInit() {
        if (cudaStreamCreateWithFlags(&g_s1, cudaStreamNonBlocking) != cudaSuccess) g_s1 = 0;
        cudaEventCreateWithFlags(&g_e0, cudaEventDisableTiming);
        cudaEventCreateWithFlags(&g_e1, cudaEventDisableTiming);
    }
};
SideStreamInit g_side_stream_init;
}

// ---------------- device scratch ----------------
__device__ __align__(16) __half g_xh   [(size_t)(NN + 64) * FIN]; // fp16 x (padded)
__device__ __align__(16) __half g_h1f16[(size_t)NN * C1];         // fp16 x@W1
__device__ __align__(16) __half g_out1h[(size_t)(NN + 64) * C1];  // fp16 LN(elu(agg1+b1)) (padded)
__device__ __align__(16) __half g_h2f16[(size_t)NN * HID];        // fp16 h1n@W2
__device__ __align__(16) float g_es1[NN * 4];
__device__ __align__(16) float g_ed1[NN * 4];
__device__ float g_es2[NN], g_ed2[NN];
__device__ float g_sent[HID];
// CSR (g_deg zero-initialized at load; re-zeroed by agg1 each call)
__device__ int g_deg[NN];
__device__ int g_rowstart[NN + 1];
__device__ int g_fill[NN];
__device__ int g_csrc[NE];
__device__ int g_eorig[NE];

// ---------------- helpers ----------------
__device__ __forceinline__ float warp_sum(float v) {
    #pragma unroll
    for (int o = 16; o; o >>= 1) v += __shfl_xor_sync(0xffffffffu, v, o);
    return v;
}
__device__ __forceinline__ float lrelu02(float v) { return v > 0.f ? v : 0.2f * v; }
__device__ __forceinline__ float fexp(float v) { return __expf(v); }

__device__ __forceinline__ void cp_async16(void* smem, const void* gmem) {
    unsigned s = (unsigned)__cvta_generic_to_shared(smem);
    asm volatile("cp.async.cg.shared.global [%0], [%1], 16;\n" :: "r"(s), "l"(gmem));
}
__device__ __forceinline__ void cp_commit() { asm volatile("cp.async.commit_group;\n"); }
__device__ __forceinline__ void cp_wait0()  { asm volatile("cp.async.wait_group 0;\n"); }

__device__ __forceinline__ uint4 packh8(float4 a, float4 b) {
    __half2 h0 = __floats2half2_rn(a.x, a.y);
    __half2 h1 = __floats2half2_rn(a.z, a.w);
    __half2 h2 = __floats2half2_rn(b.x, b.y);
    __half2 h3 = __floats2half2_rn(b.z, b.w);
    return make_uint4(*(unsigned*)&h0, *(unsigned*)&h1, *(unsigned*)&h2, *(unsigned*)&h3);
}

// ================= x -> fp16 conversion =================
__global__ __launch_bounds__(256) void x2h(const float* __restrict__ x) {
    int i = blockIdx.x * blockDim.x + threadIdx.x;
    if (i >= NN * FIN / 8) return;
    const float4* src = (const float4*)x + i * 2;
    float4 a = src[0], b = src[1];
    ((uint4*)g_xh)[i] = packh8(a, b);
}

// ================= CSR build =================
__global__ void k_hist(const int* __restrict__ ei) {
    int e4 = blockIdx.x * blockDim.x + threadIdx.x;
    if (e4 >= NE / 4) return;
    int4 d = ((const int4*)(ei + NE))[e4];
    atomicAdd(&g_deg[d.x], 1);
    atomicAdd(&g_deg[d.y], 1);
    atomicAdd(&g_deg[d.z], 1);
    atomicAdd(&g_deg[d.w], 1);
}

__global__ void k_scan() {
    __shared__ int wsum[32];
    __shared__ int stot;
    const int t = threadIdx.x, lane = t & 31, w = t >> 5;
    int base = 0;
    for (int c = 0; c < 13; c++) {
        int i4 = c * 1024 + t;
        int4 v = (i4 < NN / 4) ? ((const int4*)g_deg)[i4] : make_int4(0, 0, 0, 0);
        int tot = v.x + v.y + v.z + v.w;
        int inc = tot;
        #pragma unroll
        for (int o = 1; o < 32; o <<= 1) {
            int x = __shfl_up_sync(0xffffffffu, inc, o);
            if (lane >= o) inc += x;
        }
        if (lane == 31) wsum[w] = inc;
        __syncthreads();
        if (w == 0) {
            int x = wsum[lane];
            int incw = x;
            #pragma unroll
            for (int o = 1; o < 32; o <<= 1) {
                int y = __shfl_up_sync(0xffffffffu, incw, o);
                if (lane >= o) incw += y;
            }
            wsum[lane] = incw;
            if (lane == 31) stot = incw;
        }
        __syncthreads();
        int excl = base + (w ? wsum[w - 1] : 0) + inc - tot;
        if (i4 < NN / 4) {
            int idx = i4 * 4;
            int e0 = excl, e1 = e0 + v.x, e2 = e1 + v.y, e3 = e2 + v.z;
            g_rowstart[idx] = e0; g_rowstart[idx + 1] = e1;
            g_rowstart[idx + 2] = e2; g_rowstart[idx + 3] = e3;
            g_fill[idx] = e0; g_fill[idx + 1] = e1;
            g_fill[idx + 2] = e2; g_fill[idx + 3] = e3;
        }
        base += stot;
        __syncthreads();
    }
    if (t == 0) g_rowstart[NN] = NE;
}

__global__ void k_fill(const int* __restrict__ ei) {
    int e4 = blockIdx.x * blockDim.x + threadIdx.x;
    if (e4 >= NE / 4) return;
    int4 s4 = ((const int4*)ei)[e4];
    int4 d4 = ((const int4*)(ei + NE))[e4];
    int e = e4 * 4;
    int p;
    p = atomicAdd(&g_fill[d4.x], 1); g_csrc[p] = s4.x; g_eorig[p] = e;
    p = atomicAdd(&g_fill[d4.y], 1); g_csrc[p] = s4.y; g_eorig[p] = e + 1;
    p = atomicAdd(&g_fill[d4.z], 1); g_csrc[p] = s4.z; g_eorig[p] = e + 2;
    p = atomicAdd(&g_fill[d4.w], 1); g_csrc[p] = s4.w; g_eorig[p] = e + 3;
}

// ================= GEMM1 tensor-core fused (fp16 A via cp.async) =================
// BM=128 BN=64 BK=16, 8 warps; A = g_xh, B = W1 (fp32->fp16 reg prefetch)
#define AS_BYTES  (128 * AS_LDM * 2)            /* 6144  */
#define BS_BYTES  (16 * BS2_LDM * 2)            /* 2304  */
#define SM_AS(st) (st ? AS_BYTES : 0)
#define SM_BS(st) (2 * AS_BYTES + (st ? BS_BYTES : 0))
#define SM_TOTAL  (8 * 16 * 36 * 4)             /* 18432 */

__global__ __launch_bounds__(256, 2) void gemm1_tc(const float* __restrict__ B,
        const float* __restrict__ asrc, const float* __restrict__ adst) {
    __shared__ __align__(16) char sm[SM_TOTAL];
    const int tid = threadIdx.x;
    const int w = tid >> 5, lane = tid & 31;
    const int bm = blockIdx.y * 128, bn = blockIdx.x * 64;

    wmma::fragment<wmma::accumulator, 16, 16, 16, float> acc[4];
    #pragma unroll
    for (int n = 0; n < 4; n++) wmma::fill_fragment(acc[n], 0.f);

    const int ar = tid >> 1, ac = (tid & 1) * 8;
    const int bkr = tid >> 4, bnc = (tid & 15) * 4;

    cp_async16((__half*)(sm + SM_AS(0)) + ar * AS_LDM + ac,
               &g_xh[(size_t)(bm + ar) * FIN + ac]);
    cp_commit();
    float4 b0 = *(const float4*)&B[(size_t)bkr * C1 + bn + bnc];

    for (int ks = 0; ks < 8; ks++) {
        const int st = ks & 1;
        __half* Asp = (__half*)(sm + SM_AS(st));
        __half* Bsp = (__half*)(sm + SM_BS(st));
        {
            __half2 p0 = __floats2half2_rn(b0.x, b0.y);
            __half2 p1 = __floats2half2_rn(b0.z, b0.w);
            *(uint2*)&Bsp[bkr * BS2_LDM + bnc] = make_uint2(*(unsigned*)&p0, *(unsigned*)&p1);
        }
        cp_wait0();
        __syncthreads();
        if (ks < 7) {
            int k0 = (ks + 1) * 16;
            cp_async16((__half*)(sm + SM_AS(st ^ 1)) + ar * AS_LDM + ac,
                       &g_xh[(size_t)(bm + ar) * FIN + k0 + ac]);
            cp_commit();
            b0 = *(const float4*)&B[(size_t)(k0 + bkr) * C1 + bn + bnc];
        }
        wmma::fragment<wmma::matrix_a, 16, 16, 16, __half, wmma::row_major> af;
        wmma::load_matrix_sync(af, &Asp[(w * 16) * AS_LDM], AS_LDM);
        #pragma unroll
        for (int n = 0; n < 4; n++) {
            wmma::fragment<wmma::matrix_b, 16, 16, 16, __half, wmma::row_major> bf;
            wmma::load_matrix_sync(bf, &Bsp[n * 16], BS2_LDM);
            wmma::mma_sync(acc[n], af, bf, acc[n]);
        }
        __syncthreads();
    }

    float* bufw = (float*)(sm + w * (16 * 36 * 4));
    const int row = lane >> 1, cb = (lane & 1) * 16;
    const int gr = bm + w * 16 + row;
    const int headg = blockIdx.x;
    float es = 0.f, ed = 0.f;
    #pragma unroll
    for (int qq = 0; qq < 2; qq++) {
        wmma::store_matrix_sync(bufw,      acc[2 * qq],     36, wmma::mem_row_major);
        wmma::store_matrix_sync(bufw + 16, acc[2 * qq + 1], 36, wmma::mem_row_major);
        __syncwarp();
        const int colg = qq * 32 + cb;
        unsigned pk[8];
        #pragma unroll
        for (int c = 0; c < 8; c++) {
            float2 v = *(float2*)&bufw[row * 36 + cb + c * 2];
            float2 sa = *(const float2*)&asrc[headg * 64 + colg + c * 2];
            float2 da = *(const float2*)&adst[headg * 64 + colg + c * 2];
            es += v.x * sa.x + v.y * sa.y;
            ed += v.x * da.x + v.y * da.y;
            __half2 hh = __floats2half2_rn(v.x, v.y);
            pk[c] = *(unsigned*)&hh;
        }
        if (gr < NN) {
            uint4* dst = (uint4*)&g_h1f16[(size_t)gr * C1 + bn + colg];
            dst[0] = make_uint4(pk[0], pk[1], pk[2], pk[3]);
            dst[1] = make_uint4(pk[4], pk[5], pk[6], pk[7]);
        }
        __syncwarp();
    }
    float es2 = es + __shfl_xor_sync(0xffffffffu, es, 1);
    float ed2 = ed + __shfl_xor_sync(0xffffffffu, ed, 1);
    if (gr < NN && (lane & 1) == 0) {
        g_es1[gr * 4 + headg] = es2;
        g_ed1[gr * 4 + headg] = ed2;
    }
}

// ================= GEMM2 tensor-core fused =================
#define AS2_BYTES (128 * AS_LDM * 2)
#define BS2_BYTES (16 * BS2_LDM * 2)
#define SM2_AS(st) (st ? AS2_BYTES : 0)
#define SM2_BS(st) (2 * AS2_BYTES + (st ? BS2_BYTES : 0))
#define SM2_TOTAL  (8 * 16 * 36 * 4)

__global__ __launch_bounds__(256) void gemm2_tc(const float* __restrict__ B,
        const float* __restrict__ asrc, const float* __restrict__ adst) {
    __shared__ __align__(16) char sm[SM2_TOTAL];
    const int tid = threadIdx.x;
    const int w = tid >> 5, lane = tid & 31;
    const int bm = blockIdx.x * 128;

    wmma::fragment<wmma::accumulator, 16, 16, 16, float> acc[4];
    #pragma unroll
    for (int n = 0; n < 4; n++) wmma::fill_fragment(acc[n], 0.f);

    const int ar = tid >> 1, ac = (tid & 1) * 8;
    const int bkr = tid >> 4, bnc = (tid & 15) * 4;

    cp_async16((__half*)(sm + SM2_AS(0)) + ar * AS_LDM + ac,
               &g_out1h[(size_t)(bm + ar) * C1 + ac]);
    cp_commit();
    float4 bb = *(const float4*)&B[(size_t)bkr * HID + bnc];

    for (int ks = 0; ks < 16; ks++) {
        const int st = ks & 1;
        __half* Asp = (__half*)(sm + SM2_AS(st));
        __half* Bsp = (__half*)(sm + SM2_BS(st));
        {
            __half2 p0 = __floats2half2_rn(bb.x, bb.y);
            __half2 p1 = __floats2half2_rn(bb.z, bb.w);
            *(uint2*)&Bsp[bkr * BS2_LDM + bnc] = make_uint2(*(unsigned*)&p0, *(unsigned*)&p1);
        }
        cp_wait0();
        __syncthreads();
        if (ks < 15) {
            int k0 = (ks + 1) * 16;
            cp_async16((__half*)(sm + SM2_AS(st ^ 1)) + ar * AS_LDM + ac,
                       &g_out1h[(size_t)(bm + ar) * C1 + k0 + ac]);
            cp_commit();
            bb = *(const float4*)&B[(size_t)(k0 + bkr) * HID + bnc];
        }
        wmma::fragment<wmma::matrix_a, 16, 16, 16, __half, wmma::row_major> af;
        wmma::load_matrix_sync(af, &Asp[(w * 16) * AS_LDM], AS_LDM);
        #pragma unroll
        for (int n = 0; n < 4; n++) {
            wmma::fragment<wmma::matrix_b, 16, 16, 16, __half, wmma::row_major> bf;
            wmma::load_matrix_sync(bf, &Bsp[n * 16], BS2_LDM);
            wmma::mma_sync(acc[n], af, bf, acc[n]);
        }
        __syncthreads();
    }

    float* bufw = (float*)(sm + w * (16 * 36 * 4));
    const int row = lane >> 1, cb = (lane & 1) * 16;
    const int gr = bm + w * 16 + row;
    float es = 0.f, ed = 0.f;
    #pragma unroll
    for (int qq = 0; qq < 2; qq++) {
        wmma::store_matrix_sync(bufw,      acc[2 * qq],     36, wmma::mem_row_major);
        wmma::store_matrix_sync(bufw + 16, acc[2 * qq + 1], 36, wmma::mem_row_major);
        __syncwarp();
        const int colg = qq * 32 + cb;
        unsigned pk[8];
        #pragma unroll
        for (int c = 0; c < 8; c++) {
            float2 v = *(float2*)&bufw[row * 36 + cb + c * 2];
            float2 sa = *(const float2*)&asrc[colg + c * 2];
            float2 da = *(const float2*)&adst[colg + c * 2];
            es += v.x * sa.x + v.y * sa.y;
            ed += v.x * da.x + v.y * da.y;
            __half2 hh = __floats2half2_rn(v.x, v.y);
            pk[c] = *(unsigned*)&hh;
        }
        if (gr < NN) {
            uint4* dst = (uint4*)&g_h2f16[(size_t)gr * HID + colg];
            dst[0] = make_uint4(pk[0], pk[1], pk[2], pk[3]);
            dst[1] = make_uint4(pk[4], pk[5], pk[6], pk[7]);
        }
        __syncwarp();
    }
    float es2 = es + __shfl_xor_sync(0xffffffffu, es, 1);
    float ed2 = ed + __shfl_xor_sync(0xffffffffu, ed, 1);
    if (gr < NN && (lane & 1) == 0) { g_es2[gr] = es2; g_ed2[gr] = ed2; }
}

// ================= layer-1 aggregation =================
__global__ __launch_bounds__(256) void agg1(const float* __restrict__ b1,
        const float* __restrict__ lng, const float* __restrict__ lnb) {
    const int lane = threadIdx.x & 31;
    const int d = blockIdx.x * 8 + (threadIdx.x >> 5);   // NN = 6250*8 exact
    const int r0 = g_rowstart[d], r1 = g_rowstart[d + 1];
    const int hh = lane & 3, q = lane >> 2;
    const int h = lane >> 3;
    const float edd = g_ed1[d * 4 + hh];
    const float ess = g_es1[d * 4 + hh];
    if (lane == 0) g_deg[d] = 0;
    const __half* __restrict__ hbase = g_h1f16 + lane * 8;

    float acc[8];
    #pragma unroll
    for (int i = 0; i < 8; i++) acc[i] = 0.f;
    float den = 0.f;
    for (int base = r0; base < r1; base += 8) {
        int cnt = min(8, r1 - base);
        int s = 0; float ex = 0.f;
        if (q < cnt) {
            s = g_csrc[base + q];
            ex = fexp(lrelu02(g_es1[s * 4 + hh] + edd));
        }
        den += ex;
        for (int q2 = 0; q2 < cnt; q2++) {
            unsigned ss = (unsigned)__shfl_sync(0xffffffffu, s, q2 * 4);
            float a = __shfl_sync(0xffffffffu, ex, q2 * 4 + h);
            uint4 pk = *(const uint4*)(hbase + (ss << 8));
            float2 f0 = __half22float2(*(__half2*)&pk.x);
            float2 f1 = __half22float2(*(__half2*)&pk.y);
            float2 f2 = __half22float2(*(__half2*)&pk.z);
            float2 f3 = __half22float2(*(__half2*)&pk.w);
            acc[0] += f0.x * a; acc[1] += f0.y * a;
            acc[2] += f1.x * a; acc[3] += f1.y * a;
            acc[4] += f2.x * a; acc[5] += f2.y * a;
            acc[6] += f3.x * a; acc[7] += f3.y * a;
        }
    }
    den += __shfl_xor_sync(0xffffffffu, den, 4);
    den += __shfl_xor_sync(0xffffffffu, den, 8);
    den += __shfl_xor_sync(0xffffffffu, den, 16);
    float exs = fexp(lrelu02(ess + edd));
    float rd = 1.f / (den + exs + 1e-16f);
    float rdh = __shfl_sync(0xffffffffu, rd, h);
    float exh = __shfl_sync(0xffffffffu, exs, h);

    uint4 pks = *(const uint4*)(hbase + ((unsigned)d << 8));
    float2 s0 = __half22float2(*(__half2*)&pks.x);
    float2 s1 = __half22float2(*(__half2*)&pks.y);
    float2 s2 = __half22float2(*(__half2*)&pks.z);
    float2 s3 = __half22float2(*(__half2*)&pks.w);
    float sf[8] = { s0.x, s0.y, s1.x, s1.y, s2.x, s2.y, s3.x, s3.y };

    float4 bb0 = ((const float4*)b1)[lane * 2], bb1 = ((const float4*)b1)[lane * 2 + 1];
    float bb[8] = { bb0.x, bb0.y, bb0.z, bb0.w, bb1.x, bb1.y, bb1.z, bb1.w };
    float v[8], sum1 = 0.f, sum2 = 0.f;
    #pragma unroll
    for (int i = 0; i < 8; i++) {
        v[i] = (acc[i] + exh * sf[i]) * rdh + bb[i];
        v[i] = v[i] > 0.f ? v[i] : (fexp(v[i]) - 1.f);
        sum1 += v[i]; sum2 += v[i] * v[i];
    }
    sum1 = warp_sum(sum1); sum2 = warp_sum(sum2);
    float mu = sum1 * (1.f / C1);
    float rs = rsqrtf(sum2 * (1.f / C1) - mu * mu + 1e-5f);
    float4 g0 = ((const float4*)lng)[lane * 2], g1 = ((const float4*)lng)[lane * 2 + 1];
    float4 q0 = ((const float4*)lnb)[lane * 2], q1 = ((const float4*)lnb)[lane * 2 + 1];
    float gg[8] = { g0.x, g0.y, g0.z, g0.w, g1.x, g1.y, g1.z, g1.w };
    float qq[8] = { q0.x, q0.y, q0.z, q0.w, q1.x, q1.y, q1.z, q1.w };
    float o[8];
    #pragma unroll
    for (int i = 0; i < 8; i++) o[i] = (v[i] - mu) * rs * gg[i] + qq[i];
    *(uint4*)&g_out1h[(size_t)d * C1 + lane * 8] =
        packh8(make_float4(o[0], o[1], o[2], o[3]),
               make_float4(o[4], o[5], o[6], o[7]));
}

// ================= layer-2 aggregation =================
__global__ __launch_bounds__(256) void agg2(const float* __restrict__ b2,
        const float* __restrict__ lng, const float* __restrict__ lnb,
        float* __restrict__ h2out, float* __restrict__ alpha_out) {
    const int lane = threadIdx.x & 31;
    const int d = blockIdx.x * 8 + (threadIdx.x >> 5);
    const int r0 = g_rowstart[d], r1 = g_rowstart[d + 1];
    const float edd = g_ed2[d];
    const __half* __restrict__ hbase = g_h2f16 + lane * 2;

    float2 acc = make_float2(0.f, 0.f);
    float den = 0.f;
    for (int base = r0; base < r1; base += 32) {
        int cnt = min(32, r1 - base);
        int s = 0; float ex = 0.f;
        if (lane < cnt) {
            s = g_csrc[base + lane];
            ex = fexp(lrelu02(g_es2[s] + edd));
        }
        den += ex;
        for (int q2 = 0; q2 < cnt; q2++) {
            unsigned ss = (unsigned)__shfl_sync(0xffffffffu, s, q2);
            float a = __shfl_sync(0xffffffffu, ex, q2);
            unsigned pk = *(const unsigned*)(hbase + (ss << 6));
            float2 v = __half22float2(*(__half2*)&pk);
            acc.x += v.x * a; acc.y += v.y * a;
        }
    }
    den = warp_sum(den);
    float exs = fexp(lrelu02(g_es2[d] + edd));
    float rd = 1.f / (den + exs + 1e-16f);
    if (lane == 0) alpha_out[NE + d] = exs * rd;
    for (int p = r0 + lane; p < r1; p += 32) {
        int sp = g_csrc[p];
        alpha_out[g_eorig[p]] = fexp(lrelu02(g_es2[sp] + edd)) * rd;
    }
    unsigned pks = *(const unsigned*)(hbase + ((unsigned)d << 6));
    float2 hs = __half22float2(*(__half2*)&pks);
    float2 bb = *(const float2*)&b2[lane * 2];
    float v0 = (acc.x + exs * hs.x) * rd + bb.x;
    float v1 = (acc.y + exs * hs.y) * rd + bb.y;
    float s1 = warp_sum(v0 + v1);
    float s2 = warp_sum(v0 * v0 + v1 * v1);
    float mu = s1 * (1.f / HID);
    float rs = rsqrtf(s2 * (1.f / HID) - mu * mu + 1e-5f);
    float2 gg = *(const float2*)&lng[lane * 2];
    float2 qq = *(const float2*)&lnb[lane * 2];
    *(float2*)&h2out[(size_t)d * HID + lane * 2] =
        make_float2((v0 - mu) * rs * gg.x + qq.x, (v1 - mu) * rs * gg.y + qq.y);
}

// ================= sentence/step path =================
__global__ __launch_bounds__(1024) void sent_kernel(const float* __restrict__ semb,
        const int* __restrict__ stepp,
        const float* __restrict__ fc0w, const float* __restrict__ fc0b,
        const float* __restrict__ fc1w, const float* __restrict__ fc1b,
        const float* __restrict__ fc2w, const float* __restrict__ fc2b,
        const float* __restrict__ lng, const float* __restrict__ lnb) {
    __shared__ float red[16][64];
    __shared__ float sh[64];
    __shared__ float st[2];
    const int t = threadIdx.x, c = t & 63, part = t >> 6;
    const float sval = (float)(stepp[0] + 1) * 0.01f;

    {
        float u = 0.f;
        int kb = part * 48;
        #pragma unroll 8
        for (int k = 0; k < 48; k++) u += semb[kb + k] * fc1w[(kb + k) * 64 + c];
        red[part][c] = u;
    }
    float steps_c = 0.f;
    {
        float tv = (t < 64) ? fmaxf(sval * fc0w[t] + fc0b[t], 0.f) : 0.f;
        float a1 = warp_sum(tv), a2 = warp_sum(tv * tv);
        if (t < 64 && (t & 31) == 0) { sh[t >> 5] = a1; sh[2 + (t >> 5)] = a2; }
        __syncthreads();
        float mu = (sh[0] + sh[1]) / 64.f;
        float rs = rsqrtf((sh[2] + sh[3]) / 64.f - mu * mu + 1e-5f);
        if (t < 64) steps_c = (tv - mu) * rs * lng[t] + lnb[t];
    }
    __syncthreads();
    if (t < 64) {
        float u = fc1b[t];
        #pragma unroll
        for (int p = 0; p < 16; p++) u += red[p][t];
        u = fmaxf(u, 0.f);
        float a1 = warp_sum(u), a2 = warp_sum(u * u);
        if ((t & 31) == 0) { st[t >> 5] = a1; red[15][62 + (t >> 5)] = a2; }
        __syncthreads();
        float mu = (st[0] + st[1]) / 64.f;
        float rs = rsqrtf((red[15][62] + red[15][63]) / 64.f - mu * mu + 1e-5f);
        sh[t] = (u - mu) * rs * lng[t] + lnb[t] + steps_c;
    } else { __syncthreads(); }
    __syncthreads();
    if (t < 256) {
        float u = 0.f;
        int kb = (part & 3) * 16;
        #pragma unroll
        for (int k = 0; k < 16; k++) u += sh[kb + k] * fc2w[(kb + k) * 64 + c];
        red[part & 3][c] = u;
    }
    __syncthreads();
    if (t < 64) {
        float u = red[0][t] + red[1][t] + red[2][t] + red[3][t] + fc2b[t];
        u = fmaxf(u, 0.f);
        float a1 = warp_sum(u), a2 = warp_sum(u * u);
        if ((t & 31) == 0) { st[t >> 5] = a1; red[15][62 + (t >> 5)] = a2; }
        __syncthreads();
        float mu = (st[0] + st[1]) / 64.f;
        float rs = rsqrtf((red[15][62] + red[15][63]) / 64.f - mu * mu + 1e-5f);
        g_sent[t] = (u - mu) * rs * lng[t] + lnb[t];
    }
}

// ================= dueling head =================
__global__ __launch_bounds__(256) void head_kernel(const float* __restrict__ h2base,
        const int* __restrict__ activep,
        const float* __restrict__ fc3w, const float* __restrict__ fc3b,
        const float* __restrict__ valw, const float* __restrict__ valb,
        const float* __restrict__ advw, const float* __restrict__ advb,
        const float* __restrict__ lnfg, const float* __restrict__ lnfb,
        const float* __restrict__ lnhg, const float* __restrict__ lnhb,
        float* __restrict__ outlogits) {
    __shared__ float sh[128];
    __shared__ float sh2[64];
    __shared__ float red[8][64];
    __shared__ float st[8];
    const int t = threadIdx.x;
    const int act = activep[0];
    {
        float a = 0.f;
        if (t < 128) {
            a = (t < 64) ? h2base[(size_t)act * 64 + t] : g_sent[t - 64];
        }
        float a1 = warp_sum(t < 128 ? a : 0.f), a2 = warp_sum(t < 128 ? a * a : 0.f);
        if (t < 128 && (t & 31) == 0) { st[t >> 5] = a1; st[4 + (t >> 5)] = a2; }
        __syncthreads();
        float mu = (st[0] + st[1] + st[2] + st[3]) / 128.f;
        float rs = rsqrtf((st[4] + st[5] + st[6] + st[7]) / 128.f - mu * mu + 1e-5f);
        if (t < 128) sh[t] = (a - mu) * rs * lnfg[t] + lnfb[t];
    }
    __syncthreads();
    {
        const int c = t & 63, part = t >> 6;
        float u = 0.f;
        int kb = part * 32;
        #pragma unroll 8
        for (int k = 0; k < 32; k++) u += sh[kb + k] * fc3w[(kb + k) * 64 + c];
        red[part][c] = u;
    }
    __syncthreads();
    if (t < 64) {
        float u = red[0][t] + red[1][t] + red[2][t] + red[3][t] + fc3b[t];
        u = fmaxf(u, 0.f);
        float a1 = warp_sum(u), a2 = warp_sum(u * u);
        if ((t & 31) == 0) { st[t >> 5] = a1; st[4 + (t >> 5)] = a2; }
        __syncthreads();
        float mu = (st[0] + st[1]) / 64.f;
        float rs = rsqrtf((st[4] + st[5]) / 64.f - mu * mu + 1e-5f);
        sh2[t] = (u - mu) * rs * lnhg[t] + lnhb[t];
    } else { __syncthreads(); }
    __syncthreads();
    {
        float pv = (t < 64) ? sh2[t] * valw[t] : 0.f;
        float a1 = warp_sum(pv);
        if (t < 64 && (t & 31) == 0) st[6 + (t >> 5)] = a1;
    }
    {
        const int c = t & 31, part = t >> 5;
        float u = 0.f;
        int kb = part * 8;
        #pragma unroll
        for (int k = 0; k < 8; k++) u += sh2[kb + k] * advw[(kb + k) * 32 + c];
        red[part][c] = u;
    }
    __syncthreads();
    float val = st[6] + st[7] + valb[0];
    float advv = 0.f;
    if (t < 32) {
        advv = advb[t];
        #pragma unroll
        for (int p = 0; p < 8; p++) advv += red[p][t];
    }
    float m = warp_sum(t < 32 ? advv : 0.f) * (1.f / 32.f);
    if (t < 32) outlogits[t] = tanhf(val + advv - m);
}

// ================= launch (fork/join: CSR+sent on side stream ∥ x2h+GEMM1 on main) =====
extern "C" void kernel_launch(void* const* d_in, const int* in_sizes, int n_in,
                              void* d_out, int out_size) {
    const float* x      = (const float*)d_in[0];
    const int*   ei     = (const int*)d_in[1];
    const float* semb   = (const float*)d_in[2];
    const int*   active = (const int*)d_in[3];
    const int*   step   = (const int*)d_in[4];
    const float* W1     = (const float*)d_in[5];
    const float* asrc1  = (const float*)d_in[6];
    const float* adst1  = (const float*)d_in[7];
    const float* b1     = (const float*)d_in[8];
    const float* W2     = (const float*)d_in[9];
    const float* asrc2  = (const float*)d_in[10];
    const float* adst2  = (const float*)d_in[11];
    const float* b2     = (const float*)d_in[12];
    const float* fc0w   = (const float*)d_in[13];
    const float* fc0b   = (const float*)d_in[14];
    const float* fc1w   = (const float*)d_in[15];
    const float* fc1b   = (const float*)d_in[16];
    const float* fc2w   = (const float*)d_in[17];
    const float* fc2b   = (const float*)d_in[18];
    const float* fc3w   = (const float*)d_in[19];
    const float* fc3b   = (const float*)d_in[20];
    const float* valw   = (const float*)d_in[21];
    const float* valb   = (const float*)d_in[22];
    const float* advw   = (const float*)d_in[23];
    const float* advb   = (const float*)d_in[24];
    const float* lnhg   = (const float*)d_in[25];
    const float* lnhb   = (const float*)d_in[26];
    const float* lnfg   = (const float*)d_in[27];
    const float* lnfb   = (const float*)d_in[28];
    const float* lnag   = (const float*)d_in[29];
    const float* lnab   = (const float*)d_in[30];
    float* out = (float*)d_out;

    float* h2out     = out + 32;
    float* alpha_out = out + 32 + (size_t)NN * HID;

    cudaStream_t s1 = g_s1;   // 0 fallback -> fully serial, still correct

    // fork
    cudaEventRecord(g_e0, 0);
    cudaStreamWaitEvent(s1, g_e0, 0);

    x2h<<<(NN * FIN / 8 + 255) / 256, 256>>>(x);                            // 0 main
    k_hist<<<(NE / 4 + 255) / 256, 256, 0, s1>>>(ei);                       // 1 side
    k_scan<<<1, 1024, 0, s1>>>();                                           // 2 side
    gemm1_tc<<<dim3(4, (NN + 127) / 128), 256>>>(W1, asrc1, adst1);         // 3 main <- profiled
    k_fill<<<(NE / 4 + 255) / 256, 256, 0, s1>>>(ei);                       // 4 side
    sent_kernel<<<1, 1024, 0, s1>>>(semb, step, fc0w, fc0b, fc1w, fc1b,
                                    fc2w, fc2b, lnhg, lnhb);                // 5 side
    cudaEventRecord(g_e1, s1);

    // join, then rest of the pipeline on main stream
    cudaStreamWaitEvent(0, g_e1, 0);
    agg1<<<NN / 8, 256>>>(b1, lnag, lnab);                                  // 6
    gemm2_tc<<<(NN + 127) / 128, 256>>>(W2, asrc2, adst2);                  // 7
    agg2<<<NN / 8, 256>>>(b2, lnhg, lnhb, h2out, alpha_out);                // 8
    head_kernel<<<1, 256>>>(h2out, active, fc3w, fc3b, valw, valb, advw, advb,
                            lnfg, lnfb, lnhg, lnhb, out);                   // 9
}

// round 17
// speedup vs baseline: 1.1113x; 1.0224x over previous
#include <cuda_runtime.h>
#include <cuda_fp16.h>
#include <mma.h>
#include <math.h>
#include <stdint.h>

using namespace nvcuda;

#define NN 50000
#define NE 600000
#define FIN 128
#define HID 64
#define C1 256
#define SENTD 768

#define AS_LDM 24    /* halves; 48B row stride -> conflict-free ldmatrix */
#define BS2_LDM 72   /* halves; 144B stride -> conflict-free */

// ---------------- streams/events (created at load; no device memory) ----------------
static cudaStream_t g_s1 = 0;
static cudaEvent_t g_e0 = 0, g_e1 = 0;
namespace {
struct SideStreamInit {
    SideStreamInit() {
        if (cudaStreamCreateWithFlags(&g_s1, cudaStreamNonBlocking) != cudaSuccess) g_s1 = 0;
        cudaEventCreateWithFlags(&g_e0, cudaEventDisableTiming);
        cudaEventCreateWithFlags(&g_e1, cudaEventDisableTiming);
    }
};
SideStreamInit g_side_stream_init;
}

// ---------------- device scratch ----------------
__device__ __align__(16) __half g_xh   [(size_t)(NN + 64) * FIN]; // fp16 x (padded)
__device__ __align__(16) __half g_h1f16[(size_t)NN * C1];         // fp16 x@W1
__device__ __align__(16) __half g_out1h[(size_t)(NN + 64) * C1];  // fp16 LN(elu(agg1+b1)) (padded)
__device__ __align__(16) __half g_h2f16[(size_t)NN * HID];        // fp16 h1n@W2
__device__ __align__(16) float g_es1[NN * 4];
__device__ __align__(16) float g_ed1[NN * 4];
__device__ float g_es2[NN], g_ed2[NN];
__device__ float g_sent[HID];
// CSR (g_deg zero-initialized at load; re-zeroed by agg1 each call)
__device__ int g_deg[NN];
__device__ int g_rowstart[NN + 1];
__device__ int g_fill[NN];
__device__ int g_csrc[NE];
__device__ int g_eorig[NE];

// ---------------- helpers ----------------
__device__ __forceinline__ float warp_sum(float v) {
    #pragma unroll
    for (int o = 16; o; o >>= 1) v += __shfl_xor_sync(0xffffffffu, v, o);
    return v;
}
__device__ __forceinline__ float lrelu02(float v) { return v > 0.f ? v : 0.2f * v; }
__device__ __forceinline__ float fexp(float v) { return __expf(v); }

__device__ __forceinline__ void cp_async16(void* smem, const void* gmem) {
    unsigned s = (unsigned)__cvta_generic_to_shared(smem);
    asm volatile("cp.async.cg.shared.global [%0], [%1], 16;\n" :: "r"(s), "l"(gmem));
}
__device__ __forceinline__ void cp_commit() { asm volatile("cp.async.commit_group;\n"); }
__device__ __forceinline__ void cp_wait0()  { asm volatile("cp.async.wait_group 0;\n"); }
__device__ __forceinline__ void cp_wait1()  { asm volatile("cp.async.wait_group 1;\n"); }

__device__ __forceinline__ uint4 packh8(float4 a, float4 b) {
    __half2 h0 = __floats2half2_rn(a.x, a.y);
    __half2 h1 = __floats2half2_rn(a.z, a.w);
    __half2 h2 = __floats2half2_rn(b.x, b.y);
    __half2 h3 = __floats2half2_rn(b.z, b.w);
    return make_uint4(*(unsigned*)&h0, *(unsigned*)&h1, *(unsigned*)&h2, *(unsigned*)&h3);
}

// ================= x -> fp16 conversion =================
__global__ __launch_bounds__(256) void x2h(const float* __restrict__ x) {
    int i = blockIdx.x * blockDim.x + threadIdx.x;
    if (i >= NN * FIN / 8) return;
    const float4* src = (const float4*)x + i * 2;
    float4 a = src[0], b = src[1];
    ((uint4*)g_xh)[i] = packh8(a, b);
}

// ================= CSR build =================
__global__ void k_hist(const int* __restrict__ ei) {
    int e4 = blockIdx.x * blockDim.x + threadIdx.x;
    if (e4 >= NE / 4) return;
    int4 d = ((const int4*)(ei + NE))[e4];
    atomicAdd(&g_deg[d.x], 1);
    atomicAdd(&g_deg[d.y], 1);
    atomicAdd(&g_deg[d.z], 1);
    atomicAdd(&g_deg[d.w], 1);
}

__global__ void k_scan() {
    __shared__ int wsum[32];
    __shared__ int stot;
    const int t = threadIdx.x, lane = t & 31, w = t >> 5;
    int base = 0;
    for (int c = 0; c < 13; c++) {
        int i4 = c * 1024 + t;
        int4 v = (i4 < NN / 4) ? ((const int4*)g_deg)[i4] : make_int4(0, 0, 0, 0);
        int tot = v.x + v.y + v.z + v.w;
        int inc = tot;
        #pragma unroll
        for (int o = 1; o < 32; o <<= 1) {
            int x = __shfl_up_sync(0xffffffffu, inc, o);
            if (lane >= o) inc += x;
        }
        if (lane == 31) wsum[w] = inc;
        __syncthreads();
        if (w == 0) {
            int x = wsum[lane];
            int incw = x;
            #pragma unroll
            for (int o = 1; o < 32; o <<= 1) {
                int y = __shfl_up_sync(0xffffffffu, incw, o);
                if (lane >= o) incw += y;
            }
            wsum[lane] = incw;
            if (lane == 31) stot = incw;
        }
        __syncthreads();
        int excl = base + (w ? wsum[w - 1] : 0) + inc - tot;
        if (i4 < NN / 4) {
            int idx = i4 * 4;
            int e0 = excl, e1 = e0 + v.x, e2 = e1 + v.y, e3 = e2 + v.z;
            g_rowstart[idx] = e0; g_rowstart[idx + 1] = e1;
            g_rowstart[idx + 2] = e2; g_rowstart[idx + 3] = e3;
            g_fill[idx] = e0; g_fill[idx + 1] = e1;
            g_fill[idx + 2] = e2; g_fill[idx + 3] = e3;
        }
        base += stot;
        __syncthreads();
    }
    if (t == 0) g_rowstart[NN] = NE;
}

__global__ void k_fill(const int* __restrict__ ei) {
    int e4 = blockIdx.x * blockDim.x + threadIdx.x;
    if (e4 >= NE / 4) return;
    int4 s4 = ((const int4*)ei)[e4];
    int4 d4 = ((const int4*)(ei + NE))[e4];
    int e = e4 * 4;
    int p;
    p = atomicAdd(&g_fill[d4.x], 1); g_csrc[p] = s4.x; g_eorig[p] = e;
    p = atomicAdd(&g_fill[d4.y], 1); g_csrc[p] = s4.y; g_eorig[p] = e + 1;
    p = atomicAdd(&g_fill[d4.z], 1); g_csrc[p] = s4.z; g_eorig[p] = e + 2;
    p = atomicAdd(&g_fill[d4.w], 1); g_csrc[p] = s4.w; g_eorig[p] = e + 3;
}

// ================= GEMM1 tensor-core fused (fp16 A via 3-stage cp.async ring) ==========
// BM=128 BN=64 BK=16, 8 warps, 2 blocks/SM
#define AS_BYTES  (128 * AS_LDM * 2)            /* 6144  */
#define BS_BYTES  (16 * BS2_LDM * 2)            /* 2304  */
#define SM_TOTAL  (3 * AS_BYTES + 2 * BS_BYTES) /* 23040 */

__global__ __launch_bounds__(256, 2) void gemm1_tc(const float* __restrict__ B,
        const float* __restrict__ asrc, const float* __restrict__ adst) {
    __shared__ __align__(16) char sm[SM_TOTAL];
    const int tid = threadIdx.x;
    const int w = tid >> 5, lane = tid & 31;
    const int bm = blockIdx.y * 128, bn = blockIdx.x * 64;

    wmma::fragment<wmma::accumulator, 16, 16, 16, float> acc[4];
    #pragma unroll
    for (int n = 0; n < 4; n++) wmma::fill_fragment(acc[n], 0.f);

    const int ar = tid >> 1, ac = (tid & 1) * 8;
    const int bkr = tid >> 4, bnc = (tid & 15) * 4;
    const __half* arow = &g_xh[(size_t)(bm + ar) * FIN + ac];

    // prologue: 2 A stages in flight
    cp_async16((__half*)(sm + 0 * AS_BYTES) + ar * AS_LDM + ac, arow);
    cp_commit();
    cp_async16((__half*)(sm + 1 * AS_BYTES) + ar * AS_LDM + ac, arow + 16);
    cp_commit();
    float4 b0 = *(const float4*)&B[(size_t)bkr * C1 + bn + bnc];

    for (int ks = 0; ks < 8; ks++) {
        const int stA = ks % 3, stB = ks & 1;
        __half* Asp = (__half*)(sm + stA * AS_BYTES);
        __half* Bsp = (__half*)(sm + 3 * AS_BYTES + stB * BS_BYTES);
        {
            __half2 p0 = __floats2half2_rn(b0.x, b0.y);
            __half2 p1 = __floats2half2_rn(b0.z, b0.w);
            *(uint2*)&Bsp[bkr * BS2_LDM + bnc] = make_uint2(*(unsigned*)&p0, *(unsigned*)&p1);
        }
        if (ks == 7) cp_wait0(); else cp_wait1();
        __syncthreads();
        if (ks < 6) {
            cp_async16((__half*)(sm + ((ks + 2) % 3) * AS_BYTES) + ar * AS_LDM + ac,
                       arow + (ks + 2) * 16);
            cp_commit();
        }
        if (ks < 7)
            b0 = *(const float4*)&B[(size_t)((ks + 1) * 16 + bkr) * C1 + bn + bnc];
        wmma::fragment<wmma::matrix_a, 16, 16, 16, __half, wmma::row_major> af;
        wmma::load_matrix_sync(af, &Asp[(w * 16) * AS_LDM], AS_LDM);
        #pragma unroll
        for (int n = 0; n < 4; n++) {
            wmma::fragment<wmma::matrix_b, 16, 16, 16, __half, wmma::row_major> bf;
            wmma::load_matrix_sync(bf, &Bsp[n * 16], BS2_LDM);
            wmma::mma_sync(acc[n], af, bf, acc[n]);
        }
        __syncthreads();
    }

    float* bufw = (float*)(sm + w * (16 * 36 * 4));
    const int row = lane >> 1, cb = (lane & 1) * 16;
    const int gr = bm + w * 16 + row;
    const int headg = blockIdx.x;
    float es = 0.f, ed = 0.f;
    #pragma unroll
    for (int qq = 0; qq < 2; qq++) {
        wmma::store_matrix_sync(bufw,      acc[2 * qq],     36, wmma::mem_row_major);
        wmma::store_matrix_sync(bufw + 16, acc[2 * qq + 1], 36, wmma::mem_row_major);
        __syncwarp();
        const int colg = qq * 32 + cb;
        unsigned pk[8];
        #pragma unroll
        for (int c = 0; c < 8; c++) {
            float2 v = *(float2*)&bufw[row * 36 + cb + c * 2];
            float2 sa = *(const float2*)&asrc[headg * 64 + colg + c * 2];
            float2 da = *(const float2*)&adst[headg * 64 + colg + c * 2];
            es += v.x * sa.x + v.y * sa.y;
            ed += v.x * da.x + v.y * da.y;
            __half2 hh = __floats2half2_rn(v.x, v.y);
            pk[c] = *(unsigned*)&hh;
        }
        if (gr < NN) {
            uint4* dst = (uint4*)&g_h1f16[(size_t)gr * C1 + bn + colg];
            dst[0] = make_uint4(pk[0], pk[1], pk[2], pk[3]);
            dst[1] = make_uint4(pk[4], pk[5], pk[6], pk[7]);
        }
        __syncwarp();
    }
    float es2 = es + __shfl_xor_sync(0xffffffffu, es, 1);
    float ed2 = ed + __shfl_xor_sync(0xffffffffu, ed, 1);
    if (gr < NN && (lane & 1) == 0) {
        g_es1[gr * 4 + headg] = es2;
        g_ed1[gr * 4 + headg] = ed2;
    }
}

// ================= GEMM2 tensor-core fused (3-stage A ring) =================
#define SM2_TOTAL  (3 * AS_BYTES + 2 * BS_BYTES)

__global__ __launch_bounds__(256) void gemm2_tc(const float* __restrict__ B,
        const float* __restrict__ asrc, const float* __restrict__ adst) {
    __shared__ __align__(16) char sm[SM2_TOTAL];
    const int tid = threadIdx.x;
    const int w = tid >> 5, lane = tid & 31;
    const int bm = blockIdx.x * 128;

    wmma::fragment<wmma::accumulator, 16, 16, 16, float> acc[4];
    #pragma unroll
    for (int n = 0; n < 4; n++) wmma::fill_fragment(acc[n], 0.f);

    const int ar = tid >> 1, ac = (tid & 1) * 8;
    const int bkr = tid >> 4, bnc = (tid & 15) * 4;
    const __half* arow = &g_out1h[(size_t)(bm + ar) * C1 + ac];

    cp_async16((__half*)(sm + 0 * AS_BYTES) + ar * AS_LDM + ac, arow);
    cp_commit();
    cp_async16((__half*)(sm + 1 * AS_BYTES) + ar * AS_LDM + ac, arow + 16);
    cp_commit();
    float4 bb = *(const float4*)&B[(size_t)bkr * HID + bnc];

    for (int ks = 0; ks < 16; ks++) {
        const int stA = ks % 3, stB = ks & 1;
        __half* Asp = (__half*)(sm + stA * AS_BYTES);
        __half* Bsp = (__half*)(sm + 3 * AS_BYTES + stB * BS_BYTES);
        {
            __half2 p0 = __floats2half2_rn(bb.x, bb.y);
            __half2 p1 = __floats2half2_rn(bb.z, bb.w);
            *(uint2*)&Bsp[bkr * BS2_LDM + bnc] = make_uint2(*(unsigned*)&p0, *(unsigned*)&p1);
        }
        if (ks == 15) cp_wait0(); else cp_wait1();
        __syncthreads();
        if (ks < 14) {
            cp_async16((__half*)(sm + ((ks + 2) % 3) * AS_BYTES) + ar * AS_LDM + ac,
                       arow + (ks + 2) * 16);
            cp_commit();
        }
        if (ks < 15)
            bb = *(const float4*)&B[(size_t)((ks + 1) * 16 + bkr) * HID + bnc];
        wmma::fragment<wmma::matrix_a, 16, 16, 16, __half, wmma::row_major> af;
        wmma::load_matrix_sync(af, &Asp[(w * 16) * AS_LDM], AS_LDM);
        #pragma unroll
        for (int n = 0; n < 4; n++) {
            wmma::fragment<wmma::matrix_b, 16, 16, 16, __half, wmma::row_major> bf;
            wmma::load_matrix_sync(bf, &Bsp[n * 16], BS2_LDM);
            wmma::mma_sync(acc[n], af, bf, acc[n]);
        }
        __syncthreads();
    }

    float* bufw = (float*)(sm + w * (16 * 36 * 4));
    const int row = lane >> 1, cb = (lane & 1) * 16;
    const int gr = bm + w * 16 + row;
    float es = 0.f, ed = 0.f;
    #pragma unroll
    for (int qq = 0; qq < 2; qq++) {
        wmma::store_matrix_sync(bufw,      acc[2 * qq],     36, wmma::mem_row_major);
        wmma::store_matrix_sync(bufw + 16, acc[2 * qq + 1], 36, wmma::mem_row_major);
        __syncwarp();
        const int colg = qq * 32 + cb;
        unsigned pk[8];
        #pragma unroll
        for (int c = 0; c < 8; c++) {
            float2 v = *(float2*)&bufw[row * 36 + cb + c * 2];
            float2 sa = *(const float2*)&asrc[colg + c * 2];
            float2 da = *(const float2*)&adst[colg + c * 2];
            es += v.x * sa.x + v.y * sa.y;
            ed += v.x * da.x + v.y * da.y;
            __half2 hh = __floats2half2_rn(v.x, v.y);
            pk[c] = *(unsigned*)&hh;
        }
        if (gr < NN) {
            uint4* dst = (uint4*)&g_h2f16[(size_t)gr * HID + colg];
            dst[0] = make_uint4(pk[0], pk[1], pk[2], pk[3]);
            dst[1] = make_uint4(pk[4], pk[5], pk[6], pk[7]);
        }
        __syncwarp();
    }
    float es2 = es + __shfl_xor_sync(0xffffffffu, es, 1);
    float ed2 = ed + __shfl_xor_sync(0xffffffffu, ed, 1);
    if (gr < NN && (lane & 1) == 0) { g_es2[gr] = es2; g_ed2[gr] = ed2; }
}

// ================= layer-1 aggregation =================
__global__ __launch_bounds__(256) void agg1(const float* __restrict__ b1,
        const float* __restrict__ lng, const float* __restrict__ lnb) {
    const int lane = threadIdx.x & 31;
    const int d = blockIdx.x * 8 + (threadIdx.x >> 5);   // NN = 6250*8 exact
    const int r0 = g_rowstart[d], r1 = g_rowstart[d + 1];
    const int hh = lane & 3, q = lane >> 2;
    const int h = lane >> 3;
    const float edd = g_ed1[d * 4 + hh];
    const float ess = g_es1[d * 4 + hh];
    if (lane == 0) g_deg[d] = 0;
    const __half* __restrict__ hbase = g_h1f16 + lane * 8;

    float acc[8];
    #pragma unroll
    for (int i = 0; i < 8; i++) acc[i] = 0.f;
    float den = 0.f;
    for (int base = r0; base < r1; base += 8) {
        int cnt = min(8, r1 - base);
        int s = 0; float ex = 0.f;
        if (q < cnt) {
            s = g_csrc[base + q];
            ex = fexp(lrelu02(g_es1[s * 4 + hh] + edd));
        }
        den += ex;
        for (int q2 = 0; q2 < cnt; q2++) {
            unsigned ss = (unsigned)__shfl_sync(0xffffffffu, s, q2 * 4);
            float a = __shfl_sync(0xffffffffu, ex, q2 * 4 + h);
            uint4 pk = *(const uint4*)(hbase + (ss << 8));
            float2 f0 = __half22float2(*(__half2*)&pk.x);
            float2 f1 = __half22float2(*(__half2*)&pk.y);
            float2 f2 = __half22float2(*(__half2*)&pk.z);
            float2 f3 = __half22float2(*(__half2*)&pk.w);
            acc[0] += f0.x * a; acc[1] += f0.y * a;
            acc[2] += f1.x * a; acc[3] += f1.y * a;
            acc[4] += f2.x * a; acc[5] += f2.y * a;
            acc[6] += f3.x * a; acc[7] += f3.y * a;
        }
    }
    den += __shfl_xor_sync(0xffffffffu, den, 4);
    den += __shfl_xor_sync(0xffffffffu, den, 8);
    den += __shfl_xor_sync(0xffffffffu, den, 16);
    float exs = fexp(lrelu02(ess + edd));
    float rd = 1.f / (den + exs + 1e-16f);
    float rdh = __shfl_sync(0xffffffffu, rd, h);
    float exh = __shfl_sync(0xffffffffu, exs, h);

    uint4 pks = *(const uint4*)(hbase + ((unsigned)d << 8));
    float2 s0 = __half22float2(*(__half2*)&pks.x);
    float2 s1 = __half22float2(*(__half2*)&pks.y);
    float2 s2 = __half22float2(*(__half2*)&pks.z);
    float2 s3 = __half22float2(*(__half2*)&pks.w);
    float sf[8] = { s0.x, s0.y, s1.x, s1.y, s2.x, s2.y, s3.x, s3.y };

    float4 bb0 = ((const float4*)b1)[lane * 2], bb1 = ((const float4*)b1)[lane * 2 + 1];
    float bb[8] = { bb0.x, bb0.y, bb0.z, bb0.w, bb1.x, bb1.y, bb1.z, bb1.w };
    float v[8], sum1 = 0.f, sum2 = 0.f;
    #pragma unroll
    for (int i = 0; i < 8; i++) {
        v[i] = (acc[i] + exh * sf[i]) * rdh + bb[i];
        v[i] = v[i] > 0.f ? v[i] : (fexp(v[i]) - 1.f);
        sum1 += v[i]; sum2 += v[i] * v[i];
    }
    sum1 = warp_sum(sum1); sum2 = warp_sum(sum2);
    float mu = sum1 * (1.f / C1);
    float rs = rsqrtf(sum2 * (1.f / C1) - mu * mu + 1e-5f);
    float4 g0 = ((const float4*)lng)[lane * 2], g1 = ((const float4*)lng)[lane * 2 + 1];
    float4 q0 = ((const float4*)lnb)[lane * 2], q1 = ((const float4*)lnb)[lane * 2 + 1];
    float gg[8] = { g0.x, g0.y, g0.z, g0.w, g1.x, g1.y, g1.z, g1.w };
    float qq[8] = { q0.x, q0.y, q0.z, q0.w, q1.x, q1.y, q1.z, q1.w };
    float o[8];
    #pragma unroll
    for (int i = 0; i < 8; i++) o[i] = (v[i] - mu) * rs * gg[i] + qq[i];
    *(uint4*)&g_out1h[(size_t)d * C1 + lane * 8] =
        packh8(make_float4(o[0], o[1], o[2], o[3]),
               make_float4(o[4], o[5], o[6], o[7]));
}

// ================= layer-2 aggregation =================
__global__ __launch_bounds__(256) void agg2(const float* __restrict__ b2,
        const float* __restrict__ lng, const float* __restrict__ lnb,
        float* __restrict__ h2out, float* __restrict__ alpha_out) {
    const int lane = threadIdx.x & 31;
    const int d = blockIdx.x * 8 + (threadIdx.x >> 5);
    const int r0 = g_rowstart[d], r1 = g_rowstart[d + 1];
    const float edd = g_ed2[d];
    const __half* __restrict__ hbase = g_h2f16 + lane * 2;

    float2 acc = make_float2(0.f, 0.f);
    float den = 0.f;
    for (int base = r0; base < r1; base += 32) {
        int cnt = min(32, r1 - base);
        int s = 0; float ex = 0.f;
        if (lane < cnt) {
            s = g_csrc[base + lane];
            ex = fexp(lrelu02(g_es2[s] + edd));
        }
        den += ex;
        for (int q2 = 0; q2 < cnt; q2++) {
            unsigned ss = (unsigned)__shfl_sync(0xffffffffu, s, q2);
            float a = __shfl_sync(0xffffffffu, ex, q2);
            unsigned pk = *(const unsigned*)(hbase + (ss << 6));
            float2 v = __half22float2(*(__half2*)&pk);
            acc.x += v.x * a; acc.y += v.y * a;
        }
    }
    den = warp_sum(den);
    float exs = fexp(lrelu02(g_es2[d] + edd));
    float rd = 1.f / (den + exs + 1e-16f);
    if (lane == 0) alpha_out[NE + d] = exs * rd;
    for (int p = r0 + lane; p < r1; p += 32) {
        int sp = g_csrc[p];
        alpha_out[g_eorig[p]] = fexp(lrelu02(g_es2[sp] + edd)) * rd;
    }
    unsigned pks = *(const unsigned*)(hbase + ((unsigned)d << 6));
    float2 hs = __half22float2(*(__half2*)&pks);
    float2 bb = *(const float2*)&b2[lane * 2];
    float v0 = (acc.x + exs * hs.x) * rd + bb.x;
    float v1 = (acc.y + exs * hs.y) * rd + bb.y;
    float s1 = warp_sum(v0 + v1);
    float s2 = warp_sum(v0 * v0 + v1 * v1);
    float mu = s1 * (1.f / HID);
    float rs = rsqrtf(s2 * (1.f / HID) - mu * mu + 1e-5f);
    float2 gg = *(const float2*)&lng[lane * 2];
    float2 qq = *(const float2*)&lnb[lane * 2];
    *(float2*)&h2out[(size_t)d * HID + lane * 2] =
        make_float2((v0 - mu) * rs * gg.x + qq.x, (v1 - mu) * rs * gg.y + qq.y);
}

// ================= sentence/step path =================
__global__ __launch_bounds__(1024) void sent_kernel(const float* __restrict__ semb,
        const int* __restrict__ stepp,
        const float* __restrict__ fc0w, const float* __restrict__ fc0b,
        const float* __restrict__ fc1w, const float* __restrict__ fc1b,
        const float* __restrict__ fc2w, const float* __restrict__ fc2b,
        const float* __restrict__ lng, const float* __restrict__ lnb) {
    __shared__ float red[16][64];
    __shared__ float sh[64];
    __shared__ float st[2];
    const int t = threadIdx.x, c = t & 63, part = t >> 6;
    const float sval = (float)(stepp[0] + 1) * 0.01f;

    {
        float u = 0.f;
        int kb = part * 48;
        #pragma unroll 8
        for (int k = 0; k < 48; k++) u += semb[kb + k] * fc1w[(kb + k) * 64 + c];
        red[part][c] = u;
    }
    float steps_c = 0.f;
    {
        float tv = (t < 64) ? fmaxf(sval * fc0w[t] + fc0b[t], 0.f) : 0.f;
        float a1 = warp_sum(tv), a2 = warp_sum(tv * tv);
        if (t < 64 && (t & 31) == 0) { sh[t >> 5] = a1; sh[2 + (t >> 5)] = a2; }
        __syncthreads();
        float mu = (sh[0] + sh[1]) / 64.f;
        float rs = rsqrtf((sh[2] + sh[3]) / 64.f - mu * mu + 1e-5f);
        if (t < 64) steps_c = (tv - mu) * rs * lng[t] + lnb[t];
    }
    __syncthreads();
    if (t < 64) {
        float u = fc1b[t];
        #pragma unroll
        for (int p = 0; p < 16; p++) u += red[p][t];
        u = fmaxf(u, 0.f);
        float a1 = warp_sum(u), a2 = warp_sum(u * u);
        if ((t & 31) == 0) { st[t >> 5] = a1; red[15][62 + (t >> 5)] = a2; }
        __syncthreads();
        float mu = (st[0] + st[1]) / 64.f;
        float rs = rsqrtf((red[15][62] + red[15][63]) / 64.f - mu * mu + 1e-5f);
        sh[t] = (u - mu) * rs * lng[t] + lnb[t] + steps_c;
    } else { __syncthreads(); }
    __syncthreads();
    if (t < 256) {
        float u = 0.f;
        int kb = (part & 3) * 16;
        #pragma unroll
        for (int k = 0; k < 16; k++) u += sh[kb + k] * fc2w[(kb + k) * 64 + c];
        red[part & 3][c] = u;
    }
    __syncthreads();
    if (t < 64) {
        float u = red[0][t] + red[1][t] + red[2][t] + red[3][t] + fc2b[t];
        u = fmaxf(u, 0.f);
        float a1 = warp_sum(u), a2 = warp_sum(u * u);
        if ((t & 31) == 0) { st[t >> 5] = a1; red[15][62 + (t >> 5)] = a2; }
        __syncthreads();
        float mu = (st[0] + st[1]) / 64.f;
        float rs = rsqrtf((red[15][62] + red[15][63]) / 64.f - mu * mu + 1e-5f);
        g_sent[t] = (u - mu) * rs * lng[t] + lnb[t];
    }
}

// ================= dueling head =================
__global__ __launch_bounds__(256) void head_kernel(const float* __restrict__ h2base,
        const int* __restrict__ activep,
        const float* __restrict__ fc3w, const float* __restrict__ fc3b,
        const float* __restrict__ valw, const float* __restrict__ valb,
        const float* __restrict__ advw, const float* __restrict__ advb,
        const float* __restrict__ lnfg, const float* __restrict__ lnfb,
        const float* __restrict__ lnhg, const float* __restrict__ lnhb,
        float* __restrict__ outlogits) {
    __shared__ float sh[128];
    __shared__ float sh2[64];
    __shared__ float red[8][64];
    __shared__ float st[8];
    const int t = threadIdx.x;
    const int act = activep[0];
    {
        float a = 0.f;
        if (t < 128) {
            a = (t < 64) ? h2base[(size_t)act * 64 + t] : g_sent[t - 64];
        }
        float a1 = warp_sum(t < 128 ? a : 0.f), a2 = warp_sum(t < 128 ? a * a : 0.f);
        if (t < 128 && (t & 31) == 0) { st[t >> 5] = a1; st[4 + (t >> 5)] = a2; }
        __syncthreads();
        float mu = (st[0] + st[1] + st[2] + st[3]) / 128.f;
        float rs = rsqrtf((st[4] + st[5] + st[6] + st[7]) / 128.f - mu * mu + 1e-5f);
        if (t < 128) sh[t] = (a - mu) * rs * lnfg[t] + lnfb[t];
    }
    __syncthreads();
    {
        const int c = t & 63, part = t >> 6;
        float u = 0.f;
        int kb = part * 32;
        #pragma unroll 8
        for (int k = 0; k < 32; k++) u += sh[kb + k] * fc3w[(kb + k) * 64 + c];
        red[part][c] = u;
    }
    __syncthreads();
    if (t < 64) {
        float u = red[0][t] + red[1][t] + red[2][t] + red[3][t] + fc3b[t];
        u = fmaxf(u, 0.f);
        float a1 = warp_sum(u), a2 = warp_sum(u * u);
        if ((t & 31) == 0) { st[t >> 5] = a1; st[4 + (t >> 5)] = a2; }
        __syncthreads();
        float mu = (st[0] + st[1]) / 64.f;
        float rs = rsqrtf((st[4] + st[5]) / 64.f - mu * mu + 1e-5f);
        sh2[t] = (u - mu) * rs * lnhg[t] + lnhb[t];
    } else { __syncthreads(); }
    __syncthreads();
    {
        float pv = (t < 64) ? sh2[t] * valw[t] : 0.f;
        float a1 = warp_sum(pv);
        if (t < 64 && (t & 31) == 0) st[6 + (t >> 5)] = a1;
    }
    {
        const int c = t & 31, part = t >> 5;
        float u = 0.f;
        int kb = part * 8;
        #pragma unroll
        for (int k = 0; k < 8; k++) u += sh2[kb + k] * advw[(kb + k) * 32 + c];
        red[part][c] = u;
    }
    __syncthreads();
    float val = st[6] + st[7] + valb[0];
    float advv = 0.f;
    if (t < 32) {
        advv = advb[t];
        #pragma unroll
        for (int p = 0; p < 8; p++) advv += red[p][t];
    }
    float m = warp_sum(t < 32 ? advv : 0.f) * (1.f / 32.f);
    if (t < 32) outlogits[t] = tanhf(val + advv - m);
}

// ================= launch (fork/join: CSR+sent on side stream ∥ x2h+GEMM1 on main) =====
extern "C" void kernel_launch(void* const* d_in, const int* in_sizes, int n_in,
                              void* d_out, int out_size) {
    const float* x      = (const float*)d_in[0];
    const int*   ei     = (const int*)d_in[1];
    const float* semb   = (const float*)d_in[2];
    const int*   active = (const int*)d_in[3];
    const int*   step   = (const int*)d_in[4];
    const float* W1     = (const float*)d_in[5];
    const float* asrc1  = (const float*)d_in[6];
    const float* adst1  = (const float*)d_in[7];
    const float* b1     = (const float*)d_in[8];
    const float* W2     = (const float*)d_in[9];
    const float* asrc2  = (const float*)d_in[10];
    const float* adst2  = (const float*)d_in[11];
    const float* b2     = (const float*)d_in[12];
    const float* fc0w   = (const float*)d_in[13];
    const float* fc0b   = (const float*)d_in[14];
    const float* fc1w   = (const float*)d_in[15];
    const float* fc1b   = (const float*)d_in[16];
    const float* fc2w   = (const float*)d_in[17];
    const float* fc2b   = (const float*)d_in[18];
    const float* fc3w   = (const float*)d_in[19];
    const float* fc3b   = (const float*)d_in[20];
    const float* valw   = (const float*)d_in[21];
    const float* valb   = (const float*)d_in[22];
    const float* advw   = (const float*)d_in[23];
    const float* advb   = (const float*)d_in[24];
    const float* lnhg   = (const float*)d_in[25];
    const float* lnhb   = (const float*)d_in[26];
    const float* lnfg   = (const float*)d_in[27];
    const float* lnfb   = (const float*)d_in[28];
    const float* lnag   = (const float*)d_in[29];
    const float* lnab   = (const float*)d_in[30];
    float* out = (float*)d_out;

    float* h2out     = out + 32;
    float* alpha_out = out + 32 + (size_t)NN * HID;

    cudaStream_t s1 = g_s1;   // 0 fallback -> fully serial, still correct

    // fork
    cudaEventRecord(g_e0, 0);
    cudaStreamWaitEvent(s1, g_e0, 0);

    x2h<<<(NN * FIN / 8 + 255) / 256, 256>>>(x);                            // 0 main
    k_hist<<<(NE / 4 + 255) / 256, 256, 0, s1>>>(ei);                       // 1 side
    k_scan<<<1, 1024, 0, s1>>>();                                           // 2 side
    gemm1_tc<<<dim3(4, (NN + 127) / 128), 256>>>(W1, asrc1, adst1);         // 3 main <- profiled
    k_fill<<<(NE / 4 + 255) / 256, 256, 0, s1>>>(ei);                       // 4 side
    sent_kernel<<<1, 1024, 0, s1>>>(semb, step, fc0w, fc0b, fc1w, fc1b,
                                    fc2w, fc2b, lnhg, lnhb);                // 5 side
    cudaEventRecord(g_e1, s1);

    // join, then rest of the pipeline on main stream
    cudaStreamWaitEvent(0, g_e1, 0);
    agg1<<<NN / 8, 256>>>(b1, lnag, lnab);                                  // 6
    gemm2_tc<<<(NN + 127) / 128, 256>>>(W2, asrc2, adst2);                  // 7
    agg2<<<NN / 8, 256>>>(b2, lnhg, lnhb, h2out, alpha_out);                // 8
    head_kernel<<<1, 256>>>(h2out, active, fc3w, fc3b, valw, valb, advw, advb,
                            lnfg, lnfb, lnhg, lnhb, out);                   // 9
}